// round 6
// baseline (speedup 1.0000x reference)
#include <cuda_runtime.h>
#include <cuda_fp16.h>
#include <math.h>
#include <stdint.h>

#define NN 50000
#define NE 800000
#define NT (NN + NE)   // edges incl. self loops
#define MAXC 256

// ---------------- scratch (static device globals; allowed) ----------------
__device__ float  g_bufA[NN * MAXC];   // 51.2 MB
__device__ float  g_bufB[NN * MAXC];   // 51.2 MB
__device__ float  g_bufC[NN * MAXC];   // 51.2 MB
__device__ __half g_xh16[NN * MAXC];   // 25.6 MB  (GAT projection outputs)
__device__ float  g_ssrc[NN * 4];
__device__ float  g_sdst[NN * 4];
__device__ int    g_deg[NN];
__device__ int    g_offs[NN + 1];
__device__ int    g_cursor[NN];
__device__ int    g_csr[NT];

// ---------------- CSR build ------------------------------------------------
__global__ void deg_count_kernel(const int* __restrict__ ei, int* __restrict__ deg) {
    int e = blockIdx.x * blockDim.x + threadIdx.x;
    if (e >= NT) return;
    int d = (e < NE) ? ei[NE + e] : (e - NE);
    atomicAdd(&deg[d], 1);
}

__global__ void scan_kernel(const int* __restrict__ deg,
                            int* __restrict__ offs,
                            int* __restrict__ cursor) {
    __shared__ int sh[1024];
    const int tid = threadIdx.x;
    const int CH = (NN + 1023) / 1024;   // 49
    const int base = tid * CH;
    int s = 0;
    for (int i = 0; i < CH; i++) {
        int idx = base + i;
        if (idx < NN) s += deg[idx];
    }
    sh[tid] = s;
    __syncthreads();
    int mine = s;
    for (int off = 1; off < 1024; off <<= 1) {
        int t2 = (tid >= off) ? sh[tid - off] : 0;
        __syncthreads();
        sh[tid] += t2;
        __syncthreads();
    }
    int run = sh[tid] - mine;   // exclusive prefix
    for (int i = 0; i < CH; i++) {
        int idx = base + i;
        if (idx < NN) {
            offs[idx] = run;
            cursor[idx] = run;
            run += deg[idx];
        }
    }
    if (tid == 1023) offs[NN] = run;
}

__global__ void csr_fill_kernel(const int* __restrict__ ei,
                                int* __restrict__ cursor,
                                int* __restrict__ csr) {
    int e = blockIdx.x * blockDim.x + threadIdx.x;
    if (e >= NT) return;
    int s, d;
    if (e < NE) { s = ei[e]; d = ei[NE + e]; }
    else        { s = d = e - NE; }
    int pos = atomicAdd(&cursor[d], 1);
    csr[pos] = s;
}

// ---------------- TF32 tensor-core GEMM ------------------------------------
// 128x128 block tile, BK=32, 8 warps (4x2), warp tile 32x64 (2x8 m16n8k8).
// C (fp32) and C16 (fp16) outputs are each optional.
__device__ __forceinline__ uint32_t f2tf(float x) {
    uint32_t u;
    asm("cvt.rna.tf32.f32 %0, %1;" : "=r"(u) : "f"(x));
    return u;
}

__device__ __forceinline__ void mma_tf32(float* c, const uint32_t* a,
                                         uint32_t b0, uint32_t b1) {
    asm volatile(
        "mma.sync.aligned.m16n8k8.row.col.f32.tf32.tf32.f32 "
        "{%0,%1,%2,%3}, {%4,%5,%6,%7}, {%8,%9}, {%0,%1,%2,%3};"
        : "+f"(c[0]), "+f"(c[1]), "+f"(c[2]), "+f"(c[3])
        : "r"(a[0]), "r"(a[1]), "r"(a[2]), "r"(a[3]), "r"(b0), "r"(b1));
}

__global__ void __launch_bounds__(256, 2)
tf32_gemm_kernel(const float* __restrict__ A, const float* __restrict__ W,
                 const float* __restrict__ bias, float* __restrict__ C,
                 __half* __restrict__ C16,
                 int M, int K, int N, int act) {
    __shared__ uint32_t sA[128 * 32];
    __shared__ uint32_t sB[32 * 128];
    const int tid = threadIdx.x;
    const int lane = tid & 31, warp = tid >> 5;
    const int wm = warp & 3, wn = warp >> 2;    // 4 warps along M, 2 along N
    const int gid = lane >> 2, tig = lane & 3;
    const int m0 = blockIdx.y * 128, n0 = blockIdx.x * 128;

    float acc[2][8][4];
#pragma unroll
    for (int i = 0; i < 2; i++)
#pragma unroll
        for (int j = 0; j < 8; j++)
#pragma unroll
            for (int q = 0; q < 4; q++) acc[i][j][q] = 0.f;

    for (int k0 = 0; k0 < K; k0 += 32) {
        // --- load A tile 128x32 (swizzle: col ^= (row&7)*4) ---
#pragma unroll
        for (int i = 0; i < 4; i++) {
            int idx = i * 256 + tid;
            int row = idx >> 3, kq = (idx & 7) * 4;
            float4 v = make_float4(0.f, 0.f, 0.f, 0.f);
            if (m0 + row < M)
                v = *(const float4*)(A + (size_t)(m0 + row) * K + k0 + kq);
            uint4 u;
            u.x = f2tf(v.x); u.y = f2tf(v.y); u.z = f2tf(v.z); u.w = f2tf(v.w);
            int sw = kq ^ ((row & 7) << 2);
            *(uint4*)&sA[row * 32 + sw] = u;
        }
        // --- load B tile 32x128 (swizzle: col ^= (k&3)*8) ---
#pragma unroll
        for (int i = 0; i < 4; i++) {
            int idx = i * 256 + tid;
            int kr = idx >> 5, nq = (idx & 31) * 4;
            float4 v = *(const float4*)(W + (size_t)(k0 + kr) * N + n0 + nq);
            uint4 u;
            u.x = f2tf(v.x); u.y = f2tf(v.y); u.z = f2tf(v.z); u.w = f2tf(v.w);
            int sw = nq ^ ((kr & 3) << 3);
            *(uint4*)&sB[kr * 128 + sw] = u;
        }
        __syncthreads();

#pragma unroll
        for (int kk = 0; kk < 32; kk += 8) {
            uint32_t a[2][4];
#pragma unroll
            for (int mt = 0; mt < 2; mt++) {
                int r = wm * 32 + mt * 16 + gid;
                int c0 = (kk + tig) ^ (gid << 2);
                int c1 = (kk + tig + 4) ^ (gid << 2);
                a[mt][0] = sA[r * 32 + c0];
                a[mt][1] = sA[(r + 8) * 32 + c0];
                a[mt][2] = sA[r * 32 + c1];
                a[mt][3] = sA[(r + 8) * 32 + c1];
            }
#pragma unroll
            for (int nt = 0; nt < 8; nt++) {
                int n = wn * 64 + nt * 8 + gid;
                int cs = n ^ (tig << 3);
                uint32_t b0 = sB[(kk + tig) * 128 + cs];
                uint32_t b1 = sB[(kk + tig + 4) * 128 + cs];
                mma_tf32(acc[0][nt], a[0], b0, b1);
                mma_tf32(acc[1][nt], a[1], b0, b1);
            }
        }
        __syncthreads();
    }

    // --- epilogue: bias + optional relu; fp32 and/or fp16 stores ---
#pragma unroll
    for (int mt = 0; mt < 2; mt++) {
        int r = m0 + wm * 32 + mt * 16 + gid;
#pragma unroll
        for (int nt = 0; nt < 8; nt++) {
            int cidx = n0 + wn * 64 + nt * 8 + tig * 2;
            float bv0 = 0.f, bv1 = 0.f;
            if (bias) { bv0 = bias[cidx]; bv1 = bias[cidx + 1]; }
            float2 v0, v1;
            v0.x = acc[mt][nt][0] + bv0;
            v0.y = acc[mt][nt][1] + bv1;
            v1.x = acc[mt][nt][2] + bv0;
            v1.y = acc[mt][nt][3] + bv1;
            if (act) {
                v0.x = fmaxf(v0.x, 0.f); v0.y = fmaxf(v0.y, 0.f);
                v1.x = fmaxf(v1.x, 0.f); v1.y = fmaxf(v1.y, 0.f);
            }
            if (C) {
                if (r < M)     *(float2*)(C + (size_t)r * N + cidx) = v0;
                if (r + 8 < M) *(float2*)(C + (size_t)(r + 8) * N + cidx) = v1;
            }
            if (C16) {
                if (r < M)
                    *(__half2*)(C16 + (size_t)r * N + cidx) = __floats2half2_rn(v0.x, v0.y);
                if (r + 8 < M)
                    *(__half2*)(C16 + (size_t)(r + 8) * N + cidx) = __floats2half2_rn(v1.x, v1.y);
            }
        }
    }
}

// ---------------- small SGEMM (64x64 tile) for gat3, fp16 output -----------
__global__ void sgemm_kernel(const float* __restrict__ A,
                             const float* __restrict__ W,
                             __half* __restrict__ C16,
                             int M, int K, int Ncols) {
    __shared__ float As[16][64];
    __shared__ float Ws[16][64];
    const int tid = threadIdx.x;
    const int tx = tid & 15, ty = tid >> 4;
    const int m0 = blockIdx.y * 64, n0 = blockIdx.x * 64;
    const int ar = tid >> 2, ac = (tid & 3) * 4;
    const int wr = tid >> 4, wc = (tid & 15) * 4;
    float acc[4][4] = {};
    for (int k0 = 0; k0 < K; k0 += 16) {
        float4 av = make_float4(0.f, 0.f, 0.f, 0.f);
        if (m0 + ar < M)
            av = *(const float4*)(A + (size_t)(m0 + ar) * K + k0 + ac);
        As[ac + 0][ar] = av.x;
        As[ac + 1][ar] = av.y;
        As[ac + 2][ar] = av.z;
        As[ac + 3][ar] = av.w;
        *(float4*)&Ws[wr][wc] = *(const float4*)(W + (size_t)(k0 + wr) * Ncols + n0 + wc);
        __syncthreads();
#pragma unroll
        for (int kk = 0; kk < 16; kk++) {
            float4 a = *(const float4*)&As[kk][ty * 4];
            float4 b = *(const float4*)&Ws[kk][tx * 4];
            float am[4] = {a.x, a.y, a.z, a.w};
            float bm[4] = {b.x, b.y, b.z, b.w};
#pragma unroll
            for (int i = 0; i < 4; i++)
#pragma unroll
                for (int j = 0; j < 4; j++)
                    acc[i][j] += am[i] * bm[j];
        }
        __syncthreads();
    }
#pragma unroll
    for (int i = 0; i < 4; i++) {
        int m = m0 + ty * 4 + i;
        if (m >= M) break;
        __half2 h0 = __floats2half2_rn(acc[i][0], acc[i][1]);
        __half2 h1 = __floats2half2_rn(acc[i][2], acc[i][3]);
        __half2* p = (__half2*)(C16 + (size_t)m * Ncols + n0 + tx * 4);
        p[0] = h0; p[1] = h1;
    }
}

// ---------------- per-node attention scores (fp16 xh): warp per (n,h) ------
template <int H>
__global__ void attn_scores_kernel(const __half* __restrict__ xh,
                                   const float* __restrict__ a_src,
                                   const float* __restrict__ a_dst,
                                   float* __restrict__ ssrc,
                                   float* __restrict__ sdst) {
    int warp = (blockIdx.x * blockDim.x + threadIdx.x) >> 5;
    int lane = threadIdx.x & 31;
    if (warp >= NN * H) return;
    int n = warp / H, h = warp % H;
    const __half2* row = (const __half2*)(xh + (size_t)n * H * 64 + h * 64);
    float2 x = __half22float2(row[lane]);
    float2 as = *(const float2*)(a_src + h * 64 + lane * 2);
    float2 ad = *(const float2*)(a_dst + h * 64 + lane * 2);
    float ps = x.x * as.x + x.y * as.y;
    float pd = x.x * ad.x + x.y * ad.y;
#pragma unroll
    for (int o = 16; o; o >>= 1) {
        ps += __shfl_xor_sync(0xffffffffu, ps, o);
        pd += __shfl_xor_sync(0xffffffffu, pd, o);
    }
    if (lane == 0) { ssrc[warp] = ps; sdst[warp] = pd; }
}

// ---------------- fused CSR aggregate (fp16 gather) ------------------------
// MODE 0: concat + bias + ELU (H=4, out 256) | MODE 1: mean2 + bias + ELU |
// MODE 2: plain + bias (H=1, out 64)
template <int H, int MODE>
__global__ void __launch_bounds__(128)
gat_aggregate(const int* __restrict__ offs,
              const int* __restrict__ csr,
              const __half* __restrict__ xh,
              const float* __restrict__ ssrc,
              const float* __restrict__ sdst,
              const float* __restrict__ bias,
              float* __restrict__ out) {
    const int TPN = H * 16;          // threads per node (4 halves each)
    const int NPB = 128 / TPN;       // nodes per block
    const int t = threadIdx.x % TPN;
    const int n = blockIdx.x * NPB + threadIdx.x / TPN;
    const int h = t >> 4;

    const float sd = sdst[n * H + h];
    const int beg = offs[n], end = offs[n + 1];

    float4 acc = make_float4(0.f, 0.f, 0.f, 0.f);
    float z = 0.f;

    // software pipeline: prefetch next edge's src index + src score
    int srcN = 0; float sN = 0.f;
    if (beg < end) {
        srcN = __ldg(&csr[beg]);
        sN = __ldg(&ssrc[srcN * H + h]);
    }
    for (int i = beg; i < end; i++) {
        int src = srcN; float sv = sN;
        if (i + 1 < end) {
            srcN = __ldg(&csr[i + 1]);
            sN = __ldg(&ssrc[srcN * H + h]);
        }
        float v = sv + sd;
        v = v > 0.f ? v : 0.2f * v;
        float e = __expf(v);
        uint2 u = *(const uint2*)(xh + (size_t)src * (H * 64) + t * 4);
        float2 f0 = __half22float2(*(const __half2*)&u.x);
        float2 f1 = __half22float2(*(const __half2*)&u.y);
        acc.x += e * f0.x;
        acc.y += e * f0.y;
        acc.z += e * f1.x;
        acc.w += e * f1.y;
        z += e;
    }

    float inv = 1.f / z;
    acc.x *= inv; acc.y *= inv; acc.z *= inv; acc.w *= inv;

    if constexpr (MODE == 0) {
        float4 bb = *(const float4*)(bias + t * 4);
        float4 v;
        v.x = acc.x + bb.x; v.y = acc.y + bb.y;
        v.z = acc.z + bb.z; v.w = acc.w + bb.w;
        v.x = v.x > 0.f ? v.x : expm1f(v.x);
        v.y = v.y > 0.f ? v.y : expm1f(v.y);
        v.z = v.z > 0.f ? v.z : expm1f(v.z);
        v.w = v.w > 0.f ? v.w : expm1f(v.w);
        *(float4*)(out + (size_t)n * 256 + t * 4) = v;
    } else if constexpr (MODE == 1) {
        // TPN == 32: one warp per node; combine h=0 and h=1 halves
        float4 o;
        o.x = __shfl_xor_sync(0xffffffffu, acc.x, 16);
        o.y = __shfl_xor_sync(0xffffffffu, acc.y, 16);
        o.z = __shfl_xor_sync(0xffffffffu, acc.z, 16);
        o.w = __shfl_xor_sync(0xffffffffu, acc.w, 16);
        if (h == 0) {
            float4 bb = *(const float4*)(bias + t * 4);
            float4 v;
            v.x = 0.5f * (acc.x + o.x) + bb.x;
            v.y = 0.5f * (acc.y + o.y) + bb.y;
            v.z = 0.5f * (acc.z + o.z) + bb.z;
            v.w = 0.5f * (acc.w + o.w) + bb.w;
            v.x = v.x > 0.f ? v.x : expm1f(v.x);
            v.y = v.y > 0.f ? v.y : expm1f(v.y);
            v.z = v.z > 0.f ? v.z : expm1f(v.z);
            v.w = v.w > 0.f ? v.w : expm1f(v.w);
            *(float4*)(out + (size_t)n * 64 + t * 4) = v;
        }
    } else {
        float4 bb = *(const float4*)(bias + t * 4);
        float4 v;
        v.x = acc.x + bb.x; v.y = acc.y + bb.y;
        v.z = acc.z + bb.z; v.w = acc.w + bb.w;
        *(float4*)(out + (size_t)n * 64 + t * 4) = v;
    }
}

// ---------------------------------------------------------------------------
static inline void run_tf32(const float* A, const float* W, const float* bias,
                            float* C, __half* C16, int M, int K, int N, int act) {
    dim3 grid(N / 128, (M + 127) / 128);
    tf32_gemm_kernel<<<grid, 256>>>(A, W, bias, C, C16, M, K, N, act);
}

extern "C" void kernel_launch(void* const* d_in, const int* in_sizes, int n_in,
                              void* d_out, int out_size) {
    const float* x    = (const float*)d_in[0];
    const int*   ei   = (const int*)d_in[1];
    const float* w1   = (const float*)d_in[2];
    const float* b1   = (const float*)d_in[3];
    const float* w2   = (const float*)d_in[4];
    const float* b2   = (const float*)d_in[5];
    const float* g1w  = (const float*)d_in[6];
    const float* g1as = (const float*)d_in[7];
    const float* g1ad = (const float*)d_in[8];
    const float* g1b  = (const float*)d_in[9];
    const float* g2w  = (const float*)d_in[10];
    const float* g2as = (const float*)d_in[11];
    const float* g2ad = (const float*)d_in[12];
    const float* g2b  = (const float*)d_in[13];
    const float* g3w  = (const float*)d_in[14];
    const float* g3as = (const float*)d_in[15];
    const float* g3ad = (const float*)d_in[16];
    const float* g3b  = (const float*)d_in[17];
    float* out = (float*)d_out;

    float *bufA, *bufB, *bufC, *ssrc, *sdst;
    __half* xh16;
    int *deg, *offs, *cursor, *csr;
    cudaGetSymbolAddress((void**)&bufA, g_bufA);
    cudaGetSymbolAddress((void**)&bufB, g_bufB);
    cudaGetSymbolAddress((void**)&bufC, g_bufC);
    cudaGetSymbolAddress((void**)&xh16, g_xh16);
    cudaGetSymbolAddress((void**)&ssrc, g_ssrc);
    cudaGetSymbolAddress((void**)&sdst, g_sdst);
    cudaGetSymbolAddress((void**)&deg, g_deg);
    cudaGetSymbolAddress((void**)&offs, g_offs);
    cudaGetSymbolAddress((void**)&cursor, g_cursor);
    cudaGetSymbolAddress((void**)&csr, g_csr);

    const int M = NN;

    // ---------------- CSR build (once, reused by all 3 GAT layers) ----------
    cudaMemsetAsync(deg, 0, NN * sizeof(int));
    deg_count_kernel<<<(NT + 255) / 256, 256>>>(ei, deg);
    scan_kernel<<<1, 1024>>>(deg, offs, cursor);
    csr_fill_kernel<<<(NT + 255) / 256, 256>>>(ei, cursor, csr);

    // ---------------- MLP (fp32 path) ----------------
    run_tf32(x,    w1, b1, bufC, nullptr, M, 256, 128, 1);   // h0
    run_tf32(bufC, w2, b2, bufB, nullptr, M, 128, 128, 1);   // h1

    // ---------------- GAT1: H=4, D=64, concat, in=bufB(128) -----------------
    run_tf32(bufB, g1w, nullptr, nullptr, xh16, M, 128, 256, 0);   // xh1 fp16
    attn_scores_kernel<4><<<(NN * 4 * 32 + 255) / 256, 256>>>(xh16, g1as, g1ad, ssrc, sdst);
    gat_aggregate<4, 0><<<NN / 2, 128>>>(offs, csr, xh16, ssrc, sdst, g1b, bufC);

    // ---------------- GAT2: H=2, D=64, mean, in=bufC(256) -------------------
    run_tf32(bufC, g2w, nullptr, nullptr, xh16, M, 256, 128, 0);   // xh2 fp16
    attn_scores_kernel<2><<<(NN * 2 * 32 + 255) / 256, 256>>>(xh16, g2as, g2ad, ssrc, sdst);
    gat_aggregate<2, 1><<<NN / 4, 128>>>(offs, csr, xh16, ssrc, sdst, g2b, bufA);

    // ---------------- GAT3: H=1, D=64, mean(identity), in=bufA(64) ----------
    {
        dim3 grid(64 / 64, (M + 63) / 64);
        sgemm_kernel<<<grid, 256>>>(bufA, g3w, xh16, M, 64, 64);   // xh3 fp16
    }
    attn_scores_kernel<1><<<(NN * 1 * 32 + 255) / 256, 256>>>(xh16, g3as, g3ad, ssrc, sdst);
    gat_aggregate<1, 2><<<NN / 8, 128>>>(offs, csr, xh16, ssrc, sdst, g3b, out);
}

// round 7
// speedup vs baseline: 1.0426x; 1.0426x over previous
#include <cuda_runtime.h>
#include <cuda_fp16.h>
#include <math.h>
#include <stdint.h>

#define NN 50000
#define NE 800000
#define NT (NN + NE)   // edges incl. self loops
#define MAXC 256

// ---------------- scratch (static device globals; allowed) ----------------
__device__ float  g_bufA[NN * MAXC];   // 51.2 MB
__device__ float  g_bufB[NN * MAXC];   // 51.2 MB
__device__ float  g_bufC[NN * MAXC];   // 51.2 MB
__device__ __half g_xh16[NN * MAXC];   // 25.6 MB  (GAT projection outputs)
__device__ float  g_ssrc[NN * 4];
__device__ float  g_sdst[NN * 4];
__device__ int    g_deg[NN];
__device__ int    g_offs[NN + 1];
__device__ int    g_cursor[NN];
__device__ int    g_csr[NT];

// ---------------- CSR build ------------------------------------------------
__global__ void deg_count_kernel(const int* __restrict__ ei, int* __restrict__ deg) {
    int e = blockIdx.x * blockDim.x + threadIdx.x;
    if (e >= NT) return;
    int d = (e < NE) ? ei[NE + e] : (e - NE);
    atomicAdd(&deg[d], 1);
}

__global__ void scan_kernel(const int* __restrict__ deg,
                            int* __restrict__ offs,
                            int* __restrict__ cursor) {
    __shared__ int sh[1024];
    const int tid = threadIdx.x;
    const int CH = (NN + 1023) / 1024;   // 49
    const int base = tid * CH;
    int s = 0;
    for (int i = 0; i < CH; i++) {
        int idx = base + i;
        if (idx < NN) s += deg[idx];
    }
    sh[tid] = s;
    __syncthreads();
    int mine = s;
    for (int off = 1; off < 1024; off <<= 1) {
        int t2 = (tid >= off) ? sh[tid - off] : 0;
        __syncthreads();
        sh[tid] += t2;
        __syncthreads();
    }
    int run = sh[tid] - mine;   // exclusive prefix
    for (int i = 0; i < CH; i++) {
        int idx = base + i;
        if (idx < NN) {
            offs[idx] = run;
            cursor[idx] = run;
            run += deg[idx];
        }
    }
    if (tid == 1023) offs[NN] = run;
}

__global__ void csr_fill_kernel(const int* __restrict__ ei,
                                int* __restrict__ cursor,
                                int* __restrict__ csr) {
    int e = blockIdx.x * blockDim.x + threadIdx.x;
    if (e >= NT) return;
    int s, d;
    if (e < NE) { s = ei[e]; d = ei[NE + e]; }
    else        { s = d = e - NE; }
    int pos = atomicAdd(&cursor[d], 1);
    csr[pos] = s;
}

// ---------------- TF32 tensor-core GEMM ------------------------------------
__device__ __forceinline__ uint32_t f2tf(float x) {
    uint32_t u;
    asm("cvt.rna.tf32.f32 %0, %1;" : "=r"(u) : "f"(x));
    return u;
}

__device__ __forceinline__ void mma_tf32(float* c, const uint32_t* a,
                                         uint32_t b0, uint32_t b1) {
    asm volatile(
        "mma.sync.aligned.m16n8k8.row.col.f32.tf32.tf32.f32 "
        "{%0,%1,%2,%3}, {%4,%5,%6,%7}, {%8,%9}, {%0,%1,%2,%3};"
        : "+f"(c[0]), "+f"(c[1]), "+f"(c[2]), "+f"(c[3])
        : "r"(a[0]), "r"(a[1]), "r"(a[2]), "r"(a[3]), "r"(b0), "r"(b1));
}

__global__ void __launch_bounds__(256, 2)
tf32_gemm_kernel(const float* __restrict__ A, const float* __restrict__ W,
                 const float* __restrict__ bias, float* __restrict__ C,
                 __half* __restrict__ C16,
                 int M, int K, int N, int act) {
    __shared__ uint32_t sA[128 * 32];
    __shared__ uint32_t sB[32 * 128];
    const int tid = threadIdx.x;
    const int lane = tid & 31, warp = tid >> 5;
    const int wm = warp & 3, wn = warp >> 2;    // 4 warps along M, 2 along N
    const int gid = lane >> 2, tig = lane & 3;
    const int m0 = blockIdx.y * 128, n0 = blockIdx.x * 128;

    float acc[2][8][4];
#pragma unroll
    for (int i = 0; i < 2; i++)
#pragma unroll
        for (int j = 0; j < 8; j++)
#pragma unroll
            for (int q = 0; q < 4; q++) acc[i][j][q] = 0.f;

    for (int k0 = 0; k0 < K; k0 += 32) {
#pragma unroll
        for (int i = 0; i < 4; i++) {
            int idx = i * 256 + tid;
            int row = idx >> 3, kq = (idx & 7) * 4;
            float4 v = make_float4(0.f, 0.f, 0.f, 0.f);
            if (m0 + row < M)
                v = *(const float4*)(A + (size_t)(m0 + row) * K + k0 + kq);
            uint4 u;
            u.x = f2tf(v.x); u.y = f2tf(v.y); u.z = f2tf(v.z); u.w = f2tf(v.w);
            int sw = kq ^ ((row & 7) << 2);
            *(uint4*)&sA[row * 32 + sw] = u;
        }
#pragma unroll
        for (int i = 0; i < 4; i++) {
            int idx = i * 256 + tid;
            int kr = idx >> 5, nq = (idx & 31) * 4;
            float4 v = *(const float4*)(W + (size_t)(k0 + kr) * N + n0 + nq);
            uint4 u;
            u.x = f2tf(v.x); u.y = f2tf(v.y); u.z = f2tf(v.z); u.w = f2tf(v.w);
            int sw = nq ^ ((kr & 3) << 3);
            *(uint4*)&sB[kr * 128 + sw] = u;
        }
        __syncthreads();

#pragma unroll
        for (int kk = 0; kk < 32; kk += 8) {
            uint32_t a[2][4];
#pragma unroll
            for (int mt = 0; mt < 2; mt++) {
                int r = wm * 32 + mt * 16 + gid;
                int c0 = (kk + tig) ^ (gid << 2);
                int c1 = (kk + tig + 4) ^ (gid << 2);
                a[mt][0] = sA[r * 32 + c0];
                a[mt][1] = sA[(r + 8) * 32 + c0];
                a[mt][2] = sA[r * 32 + c1];
                a[mt][3] = sA[(r + 8) * 32 + c1];
            }
#pragma unroll
            for (int nt = 0; nt < 8; nt++) {
                int n = wn * 64 + nt * 8 + gid;
                int cs = n ^ (tig << 3);
                uint32_t b0 = sB[(kk + tig) * 128 + cs];
                uint32_t b1 = sB[(kk + tig + 4) * 128 + cs];
                mma_tf32(acc[0][nt], a[0], b0, b1);
                mma_tf32(acc[1][nt], a[1], b0, b1);
            }
        }
        __syncthreads();
    }

#pragma unroll
    for (int mt = 0; mt < 2; mt++) {
        int r = m0 + wm * 32 + mt * 16 + gid;
#pragma unroll
        for (int nt = 0; nt < 8; nt++) {
            int cidx = n0 + wn * 64 + nt * 8 + tig * 2;
            float bv0 = 0.f, bv1 = 0.f;
            if (bias) { bv0 = bias[cidx]; bv1 = bias[cidx + 1]; }
            float2 v0, v1;
            v0.x = acc[mt][nt][0] + bv0;
            v0.y = acc[mt][nt][1] + bv1;
            v1.x = acc[mt][nt][2] + bv0;
            v1.y = acc[mt][nt][3] + bv1;
            if (act) {
                v0.x = fmaxf(v0.x, 0.f); v0.y = fmaxf(v0.y, 0.f);
                v1.x = fmaxf(v1.x, 0.f); v1.y = fmaxf(v1.y, 0.f);
            }
            if (C) {
                if (r < M)     *(float2*)(C + (size_t)r * N + cidx) = v0;
                if (r + 8 < M) *(float2*)(C + (size_t)(r + 8) * N + cidx) = v1;
            }
            if (C16) {
                if (r < M)
                    *(__half2*)(C16 + (size_t)r * N + cidx) = __floats2half2_rn(v0.x, v0.y);
                if (r + 8 < M)
                    *(__half2*)(C16 + (size_t)(r + 8) * N + cidx) = __floats2half2_rn(v1.x, v1.y);
            }
        }
    }
}

// ---------------- small SGEMM (64x64 tile) for gat3, fp16 output -----------
__global__ void sgemm_kernel(const float* __restrict__ A,
                             const float* __restrict__ W,
                             __half* __restrict__ C16,
                             int M, int K, int Ncols) {
    __shared__ float As[16][64];
    __shared__ float Ws[16][64];
    const int tid = threadIdx.x;
    const int tx = tid & 15, ty = tid >> 4;
    const int m0 = blockIdx.y * 64, n0 = blockIdx.x * 64;
    const int ar = tid >> 2, ac = (tid & 3) * 4;
    const int wr = tid >> 4, wc = (tid & 15) * 4;
    float acc[4][4] = {};
    for (int k0 = 0; k0 < K; k0 += 16) {
        float4 av = make_float4(0.f, 0.f, 0.f, 0.f);
        if (m0 + ar < M)
            av = *(const float4*)(A + (size_t)(m0 + ar) * K + k0 + ac);
        As[ac + 0][ar] = av.x;
        As[ac + 1][ar] = av.y;
        As[ac + 2][ar] = av.z;
        As[ac + 3][ar] = av.w;
        *(float4*)&Ws[wr][wc] = *(const float4*)(W + (size_t)(k0 + wr) * Ncols + n0 + wc);
        __syncthreads();
#pragma unroll
        for (int kk = 0; kk < 16; kk++) {
            float4 a = *(const float4*)&As[kk][ty * 4];
            float4 b = *(const float4*)&Ws[kk][tx * 4];
            float am[4] = {a.x, a.y, a.z, a.w};
            float bm[4] = {b.x, b.y, b.z, b.w};
#pragma unroll
            for (int i = 0; i < 4; i++)
#pragma unroll
                for (int j = 0; j < 4; j++)
                    acc[i][j] += am[i] * bm[j];
        }
        __syncthreads();
    }
#pragma unroll
    for (int i = 0; i < 4; i++) {
        int m = m0 + ty * 4 + i;
        if (m >= M) break;
        __half2 h0 = __floats2half2_rn(acc[i][0], acc[i][1]);
        __half2 h1 = __floats2half2_rn(acc[i][2], acc[i][3]);
        __half2* p = (__half2*)(C16 + (size_t)m * Ncols + n0 + tx * 4);
        p[0] = h0; p[1] = h1;
    }
}

// ---------------- per-node attention scores (fp16 xh): warp per (n,h) ------
template <int H>
__global__ void attn_scores_kernel(const __half* __restrict__ xh,
                                   const float* __restrict__ a_src,
                                   const float* __restrict__ a_dst,
                                   float* __restrict__ ssrc,
                                   float* __restrict__ sdst) {
    int warp = (blockIdx.x * blockDim.x + threadIdx.x) >> 5;
    int lane = threadIdx.x & 31;
    if (warp >= NN * H) return;
    int n = warp / H, h = warp % H;
    const __half2* row = (const __half2*)(xh + (size_t)n * H * 64 + h * 64);
    float2 x = __half22float2(row[lane]);
    float2 as = *(const float2*)(a_src + h * 64 + lane * 2);
    float2 ad = *(const float2*)(a_dst + h * 64 + lane * 2);
    float ps = x.x * as.x + x.y * as.y;
    float pd = x.x * ad.x + x.y * ad.y;
#pragma unroll
    for (int o = 16; o; o >>= 1) {
        ps += __shfl_xor_sync(0xffffffffu, ps, o);
        pd += __shfl_xor_sync(0xffffffffu, pd, o);
    }
    if (lane == 0) { ssrc[warp] = ps; sdst[warp] = pd; }
}

// ---------------- fused CSR aggregate, 4-edge unrolled batches -------------
// MODE 0: concat + bias + ELU (H=4, out 256) | MODE 1: mean2 + bias + ELU |
// MODE 2: plain + bias (H=1, out 64)
template <int H, int MODE>
__global__ void __launch_bounds__(128)
gat_aggregate(const int* __restrict__ offs,
              const int* __restrict__ csr,
              const __half* __restrict__ xh,
              const float* __restrict__ ssrc,
              const float* __restrict__ sdst,
              const float* __restrict__ bias,
              float* __restrict__ out) {
    const int TPN = H * 16;          // threads per node (4 halves each)
    const int NPB = 128 / TPN;       // nodes per block
    const int t = threadIdx.x % TPN;
    const int n = blockIdx.x * NPB + threadIdx.x / TPN;
    const int h = t >> 4;

    const float sd = sdst[n * H + h];
    const int beg = offs[n], end = offs[n + 1];

    float4 acc = make_float4(0.f, 0.f, 0.f, 0.f);
    float z = 0.f;

    int i = beg;
    // ---- 4-edge batches: all loads in each class are independent ----
    for (; i + 3 < end; i += 4) {
        int s0 = __ldg(&csr[i]);
        int s1 = __ldg(&csr[i + 1]);
        int s2 = __ldg(&csr[i + 2]);
        int s3 = __ldg(&csr[i + 3]);
        float v0 = __ldg(&ssrc[s0 * H + h]);
        float v1 = __ldg(&ssrc[s1 * H + h]);
        float v2 = __ldg(&ssrc[s2 * H + h]);
        float v3 = __ldg(&ssrc[s3 * H + h]);
        uint2 u0 = *(const uint2*)(xh + (size_t)s0 * (H * 64) + t * 4);
        uint2 u1 = *(const uint2*)(xh + (size_t)s1 * (H * 64) + t * 4);
        uint2 u2 = *(const uint2*)(xh + (size_t)s2 * (H * 64) + t * 4);
        uint2 u3 = *(const uint2*)(xh + (size_t)s3 * (H * 64) + t * 4);

        v0 += sd; v0 = v0 > 0.f ? v0 : 0.2f * v0; float e0 = __expf(v0);
        v1 += sd; v1 = v1 > 0.f ? v1 : 0.2f * v1; float e1 = __expf(v1);
        v2 += sd; v2 = v2 > 0.f ? v2 : 0.2f * v2; float e2 = __expf(v2);
        v3 += sd; v3 = v3 > 0.f ? v3 : 0.2f * v3; float e3 = __expf(v3);

        float2 a0 = __half22float2(*(const __half2*)&u0.x);
        float2 b0 = __half22float2(*(const __half2*)&u0.y);
        float2 a1 = __half22float2(*(const __half2*)&u1.x);
        float2 b1 = __half22float2(*(const __half2*)&u1.y);
        float2 a2 = __half22float2(*(const __half2*)&u2.x);
        float2 b2 = __half22float2(*(const __half2*)&u2.y);
        float2 a3 = __half22float2(*(const __half2*)&u3.x);
        float2 b3 = __half22float2(*(const __half2*)&u3.y);

        acc.x += e0 * a0.x + e1 * a1.x + e2 * a2.x + e3 * a3.x;
        acc.y += e0 * a0.y + e1 * a1.y + e2 * a2.y + e3 * a3.y;
        acc.z += e0 * b0.x + e1 * b1.x + e2 * b2.x + e3 * b3.x;
        acc.w += e0 * b0.y + e1 * b1.y + e2 * b2.y + e3 * b3.y;
        z += (e0 + e1) + (e2 + e3);
    }
    // ---- scalar tail ----
    for (; i < end; i++) {
        int src = __ldg(&csr[i]);
        float v = __ldg(&ssrc[src * H + h]) + sd;
        v = v > 0.f ? v : 0.2f * v;
        float e = __expf(v);
        uint2 u = *(const uint2*)(xh + (size_t)src * (H * 64) + t * 4);
        float2 f0 = __half22float2(*(const __half2*)&u.x);
        float2 f1 = __half22float2(*(const __half2*)&u.y);
        acc.x += e * f0.x;
        acc.y += e * f0.y;
        acc.z += e * f1.x;
        acc.w += e * f1.y;
        z += e;
    }

    float inv = 1.f / z;
    acc.x *= inv; acc.y *= inv; acc.z *= inv; acc.w *= inv;

    if constexpr (MODE == 0) {
        float4 bb = *(const float4*)(bias + t * 4);
        float4 v;
        v.x = acc.x + bb.x; v.y = acc.y + bb.y;
        v.z = acc.z + bb.z; v.w = acc.w + bb.w;
        v.x = v.x > 0.f ? v.x : expm1f(v.x);
        v.y = v.y > 0.f ? v.y : expm1f(v.y);
        v.z = v.z > 0.f ? v.z : expm1f(v.z);
        v.w = v.w > 0.f ? v.w : expm1f(v.w);
        *(float4*)(out + (size_t)n * 256 + t * 4) = v;
    } else if constexpr (MODE == 1) {
        float4 o;
        o.x = __shfl_xor_sync(0xffffffffu, acc.x, 16);
        o.y = __shfl_xor_sync(0xffffffffu, acc.y, 16);
        o.z = __shfl_xor_sync(0xffffffffu, acc.z, 16);
        o.w = __shfl_xor_sync(0xffffffffu, acc.w, 16);
        if (h == 0) {
            float4 bb = *(const float4*)(bias + t * 4);
            float4 v;
            v.x = 0.5f * (acc.x + o.x) + bb.x;
            v.y = 0.5f * (acc.y + o.y) + bb.y;
            v.z = 0.5f * (acc.z + o.z) + bb.z;
            v.w = 0.5f * (acc.w + o.w) + bb.w;
            v.x = v.x > 0.f ? v.x : expm1f(v.x);
            v.y = v.y > 0.f ? v.y : expm1f(v.y);
            v.z = v.z > 0.f ? v.z : expm1f(v.z);
            v.w = v.w > 0.f ? v.w : expm1f(v.w);
            *(float4*)(out + (size_t)n * 64 + t * 4) = v;
        }
    } else {
        float4 bb = *(const float4*)(bias + t * 4);
        float4 v;
        v.x = acc.x + bb.x; v.y = acc.y + bb.y;
        v.z = acc.z + bb.z; v.w = acc.w + bb.w;
        *(float4*)(out + (size_t)n * 64 + t * 4) = v;
    }
}

// ---------------------------------------------------------------------------
static inline void run_tf32(const float* A, const float* W, const float* bias,
                            float* C, __half* C16, int M, int K, int N, int act) {
    dim3 grid(N / 128, (M + 127) / 128);
    tf32_gemm_kernel<<<grid, 256>>>(A, W, bias, C, C16, M, K, N, act);
}

extern "C" void kernel_launch(void* const* d_in, const int* in_sizes, int n_in,
                              void* d_out, int out_size) {
    const float* x    = (const float*)d_in[0];
    const int*   ei   = (const int*)d_in[1];
    const float* w1   = (const float*)d_in[2];
    const float* b1   = (const float*)d_in[3];
    const float* w2   = (const float*)d_in[4];
    const float* b2   = (const float*)d_in[5];
    const float* g1w  = (const float*)d_in[6];
    const float* g1as = (const float*)d_in[7];
    const float* g1ad = (const float*)d_in[8];
    const float* g1b  = (const float*)d_in[9];
    const float* g2w  = (const float*)d_in[10];
    const float* g2as = (const float*)d_in[11];
    const float* g2ad = (const float*)d_in[12];
    const float* g2b  = (const float*)d_in[13];
    const float* g3w  = (const float*)d_in[14];
    const float* g3as = (const float*)d_in[15];
    const float* g3ad = (const float*)d_in[16];
    const float* g3b  = (const float*)d_in[17];
    float* out = (float*)d_out;

    float *bufA, *bufB, *bufC, *ssrc, *sdst;
    __half* xh16;
    int *deg, *offs, *cursor, *csr;
    cudaGetSymbolAddress((void**)&bufA, g_bufA);
    cudaGetSymbolAddress((void**)&bufB, g_bufB);
    cudaGetSymbolAddress((void**)&bufC, g_bufC);
    cudaGetSymbolAddress((void**)&xh16, g_xh16);
    cudaGetSymbolAddress((void**)&ssrc, g_ssrc);
    cudaGetSymbolAddress((void**)&sdst, g_sdst);
    cudaGetSymbolAddress((void**)&deg, g_deg);
    cudaGetSymbolAddress((void**)&offs, g_offs);
    cudaGetSymbolAddress((void**)&cursor, g_cursor);
    cudaGetSymbolAddress((void**)&csr, g_csr);

    const int M = NN;

    // ---------------- CSR build (once, reused by all 3 GAT layers) ----------
    cudaMemsetAsync(deg, 0, NN * sizeof(int));
    deg_count_kernel<<<(NT + 255) / 256, 256>>>(ei, deg);
    scan_kernel<<<1, 1024>>>(deg, offs, cursor);
    csr_fill_kernel<<<(NT + 255) / 256, 256>>>(ei, cursor, csr);

    // ---------------- MLP (fp32 path) ----------------
    run_tf32(x,    w1, b1, bufC, nullptr, M, 256, 128, 1);   // h0
    run_tf32(bufC, w2, b2, bufB, nullptr, M, 128, 128, 1);   // h1

    // ---------------- GAT1: H=4, D=64, concat, in=bufB(128) -----------------
    run_tf32(bufB, g1w, nullptr, nullptr, xh16, M, 128, 256, 0);   // xh1 fp16
    attn_scores_kernel<4><<<(NN * 4 * 32 + 255) / 256, 256>>>(xh16, g1as, g1ad, ssrc, sdst);
    gat_aggregate<4, 0><<<NN / 2, 128>>>(offs, csr, xh16, ssrc, sdst, g1b, bufC);

    // ---------------- GAT2: H=2, D=64, mean, in=bufC(256) -------------------
    run_tf32(bufC, g2w, nullptr, nullptr, xh16, M, 256, 128, 0);   // xh2 fp16
    attn_scores_kernel<2><<<(NN * 2 * 32 + 255) / 256, 256>>>(xh16, g2as, g2ad, ssrc, sdst);
    gat_aggregate<2, 1><<<NN / 4, 128>>>(offs, csr, xh16, ssrc, sdst, g2b, bufA);

    // ---------------- GAT3: H=1, D=64, mean(identity), in=bufA(64) ----------
    {
        dim3 grid(64 / 64, (M + 63) / 64);
        sgemm_kernel<<<grid, 256>>>(bufA, g3w, xh16, M, 64, 64);   // xh3 fp16
    }
    attn_scores_kernel<1><<<(NN * 1 * 32 + 255) / 256, 256>>>(xh16, g3as, g3ad, ssrc, sdst);
    gat_aggregate<1, 2><<<NN / 8, 128>>>(offs, csr, xh16, ssrc, sdst, g3b, out);
}

// round 11
// speedup vs baseline: 1.0726x; 1.0288x over previous
#include <cuda_runtime.h>
#include <cuda_fp16.h>
#include <math.h>
#include <stdint.h>

#define NN 50000
#define NE 800000
#define NT (NN + NE)   // edges incl. self loops
#define MAXC 256

// ---------------- scratch (static device globals; allowed) ----------------
__device__ float  g_bufA[NN * MAXC];   // 51.2 MB
__device__ float  g_bufB[NN * MAXC];   // 51.2 MB
__device__ float  g_bufC[NN * MAXC];   // 51.2 MB
__device__ __half g_xh16[NN * MAXC];   // 25.6 MB  (GAT projection outputs)
__device__ float  g_ssrc[NN * 4];
__device__ float  g_sdst[NN * 4];
__device__ int    g_deg[NN];
__device__ int    g_offs[NN + 1];
__device__ int    g_cursor[NN];
__device__ int    g_csr[NT];
// tf32-rounded weight copies
__device__ float  g_w1r[256 * 128];
__device__ float  g_w2r[128 * 128];
__device__ float  g_g1wr[128 * 256];
__device__ float  g_g2wr[256 * 128];

// ---------------- tf32 helpers ---------------------------------------------
__device__ __forceinline__ uint32_t f2tf(float x) {
    uint32_t u;
    asm("cvt.rna.tf32.f32 %0, %1;" : "=r"(u) : "f"(x));
    return u;
}
__device__ __forceinline__ float f2tf_f(float x) { return __uint_as_float(f2tf(x)); }

__global__ void round_tf32_vec4(const float* __restrict__ in,
                                float* __restrict__ out, int n4) {
    int i = blockIdx.x * blockDim.x + threadIdx.x;
    if (i >= n4) return;
    float4 v = ((const float4*)in)[i];
    uint4 u;
    u.x = f2tf(v.x); u.y = f2tf(v.y); u.z = f2tf(v.z); u.w = f2tf(v.w);
    ((uint4*)out)[i] = u;
}

// ---------------- CSR build ------------------------------------------------
__global__ void deg_count_kernel(const int* __restrict__ ei, int* __restrict__ deg) {
    int e = blockIdx.x * blockDim.x + threadIdx.x;
    if (e >= NT) return;
    int d = (e < NE) ? ei[NE + e] : (e - NE);
    atomicAdd(&deg[d], 1);
}

__global__ void scan_kernel(const int* __restrict__ deg,
                            int* __restrict__ offs,
                            int* __restrict__ cursor) {
    __shared__ int sh[1024];
    const int tid = threadIdx.x;
    const int CH = (NN + 1023) / 1024;   // 49
    const int base = tid * CH;
    int s = 0;
    for (int i = 0; i < CH; i++) {
        int idx = base + i;
        if (idx < NN) s += deg[idx];
    }
    sh[tid] = s;
    __syncthreads();
    int mine = s;
    for (int off = 1; off < 1024; off <<= 1) {
        int t2 = (tid >= off) ? sh[tid - off] : 0;
        __syncthreads();
        sh[tid] += t2;
        __syncthreads();
    }
    int run = sh[tid] - mine;   // exclusive prefix
    for (int i = 0; i < CH; i++) {
        int idx = base + i;
        if (idx < NN) {
            offs[idx] = run;
            cursor[idx] = run;
            run += deg[idx];
        }
    }
    if (tid == 1023) offs[NN] = run;
}

__global__ void csr_fill_kernel(const int* __restrict__ ei,
                                int* __restrict__ cursor,
                                int* __restrict__ csr) {
    int e = blockIdx.x * blockDim.x + threadIdx.x;
    if (e >= NT) return;
    int s, d;
    if (e < NE) { s = ei[e]; d = ei[NE + e]; }
    else        { s = d = e - NE; }
    int pos = atomicAdd(&cursor[d], 1);
    csr[pos] = s;
}

// ---------------- TF32 tensor-core GEMM, cp.async 2-stage ------------------
// Inputs A,W must be pre-rounded to tf32-representable fp32.
__device__ __forceinline__ void mma_tf32(float* c, const uint32_t* a,
                                         uint32_t b0, uint32_t b1) {
    asm volatile(
        "mma.sync.aligned.m16n8k8.row.col.f32.tf32.tf32.f32 "
        "{%0,%1,%2,%3}, {%4,%5,%6,%7}, {%8,%9}, {%0,%1,%2,%3};"
        : "+f"(c[0]), "+f"(c[1]), "+f"(c[2]), "+f"(c[3])
        : "r"(a[0]), "r"(a[1]), "r"(a[2]), "r"(a[3]), "r"(b0), "r"(b1));
}

__device__ __forceinline__ void cp16(uint32_t daddr, const void* src, int nbytes) {
    asm volatile("cp.async.cg.shared.global [%0], [%1], 16, %2;"
                 :: "r"(daddr), "l"(src), "r"(nbytes) : "memory");
}

__global__ void __launch_bounds__(256, 2)
tf32_gemm_kernel(const float* __restrict__ A, const float* __restrict__ W,
                 const float* __restrict__ bias, float* __restrict__ C,
                 __half* __restrict__ C16,
                 int M, int K, int N, int act) {
    extern __shared__ float smem[];   // [2 stages][A 4096 | B 4096] = 64 KB
    const int tid = threadIdx.x;
    const int lane = tid & 31, warp = tid >> 5;
    const int wm = warp & 3, wn = warp >> 2;    // 4 warps along M, 2 along N
    const int gid = lane >> 2, tig = lane & 3;
    const int m0 = blockIdx.y * 128, n0 = blockIdx.x * 128;

    float acc[2][8][4];
#pragma unroll
    for (int i = 0; i < 2; i++)
#pragma unroll
        for (int j = 0; j < 8; j++)
#pragma unroll
            for (int q = 0; q < 4; q++) acc[i][j][q] = 0.f;

    // per-thread load coords (4 chunks each for A and B)
    const int a_row = tid >> 1;                 // used at idx = i*256+tid
    const int nIter = K >> 5;

    auto load_stage = [&](int s, int k0) {
        float* sA = smem + s * 4096;
        float* sB = smem + 8192 + s * 4096;
#pragma unroll
        for (int i = 0; i < 4; i++) {
            int idx = i * 256 + tid;
            int row = idx >> 3, kq = (idx & 7) * 4;
            int ok = (m0 + row < M);
            const float* src = A + (size_t)(m0 + (ok ? row : 0)) * K + k0 + kq;
            int sw = kq ^ ((row & 7) << 2);
            cp16((uint32_t)__cvta_generic_to_shared(sA + row * 32 + sw), src, ok ? 16 : 0);
        }
#pragma unroll
        for (int i = 0; i < 4; i++) {
            int idx = i * 256 + tid;
            int kr = idx >> 5, nq = (idx & 31) * 4;
            int sw = nq ^ ((kr & 3) << 3);
            cp16((uint32_t)__cvta_generic_to_shared(sB + kr * 128 + sw),
                 W + (size_t)(k0 + kr) * N + n0 + nq, 16);
        }
    };

    load_stage(0, 0);
    asm volatile("cp.async.commit_group;" ::: "memory");

    for (int it = 0; it < nIter; it++) {
        if (it + 1 < nIter) load_stage((it + 1) & 1, (it + 1) << 5);
        asm volatile("cp.async.commit_group;" ::: "memory");
        asm volatile("cp.async.wait_group 1;" ::: "memory");
        __syncthreads();

        const float* sA = smem + (it & 1) * 4096;
        const float* sB = smem + 8192 + (it & 1) * 4096;
#pragma unroll
        for (int kk = 0; kk < 32; kk += 8) {
            uint32_t a[2][4];
#pragma unroll
            for (int mt = 0; mt < 2; mt++) {
                int r = wm * 32 + mt * 16 + gid;
                int c0 = (kk + tig) ^ (gid << 2);
                int c1 = (kk + tig + 4) ^ (gid << 2);
                a[mt][0] = __float_as_uint(sA[r * 32 + c0]);
                a[mt][1] = __float_as_uint(sA[(r + 8) * 32 + c0]);
                a[mt][2] = __float_as_uint(sA[r * 32 + c1]);
                a[mt][3] = __float_as_uint(sA[(r + 8) * 32 + c1]);
            }
#pragma unroll
            for (int nt = 0; nt < 8; nt++) {
                int n = wn * 64 + nt * 8 + gid;
                int cs = n ^ (tig << 3);
                uint32_t b0 = __float_as_uint(sB[(kk + tig) * 128 + cs]);
                uint32_t b1 = __float_as_uint(sB[(kk + tig + 4) * 128 + cs]);
                mma_tf32(acc[0][nt], a[0], b0, b1);
                mma_tf32(acc[1][nt], a[1], b0, b1);
            }
        }
        __syncthreads();
    }
    (void)a_row;

    // --- epilogue: bias + optional relu; C stored tf32-rounded -------------
#pragma unroll
    for (int mt = 0; mt < 2; mt++) {
        int r = m0 + wm * 32 + mt * 16 + gid;
#pragma unroll
        for (int nt = 0; nt < 8; nt++) {
            int cidx = n0 + wn * 64 + nt * 8 + tig * 2;
            float bv0 = 0.f, bv1 = 0.f;
            if (bias) { bv0 = bias[cidx]; bv1 = bias[cidx + 1]; }
            float2 v0, v1;
            v0.x = acc[mt][nt][0] + bv0;
            v0.y = acc[mt][nt][1] + bv1;
            v1.x = acc[mt][nt][2] + bv0;
            v1.y = acc[mt][nt][3] + bv1;
            if (act) {
                v0.x = fmaxf(v0.x, 0.f); v0.y = fmaxf(v0.y, 0.f);
                v1.x = fmaxf(v1.x, 0.f); v1.y = fmaxf(v1.y, 0.f);
            }
            if (C) {
                float2 r0, r1;
                r0.x = f2tf_f(v0.x); r0.y = f2tf_f(v0.y);
                r1.x = f2tf_f(v1.x); r1.y = f2tf_f(v1.y);
                if (r < M)     *(float2*)(C + (size_t)r * N + cidx) = r0;
                if (r + 8 < M) *(float2*)(C + (size_t)(r + 8) * N + cidx) = r1;
            }
            if (C16) {
                if (r < M)
                    *(__half2*)(C16 + (size_t)r * N + cidx) = __floats2half2_rn(v0.x, v0.y);
                if (r + 8 < M)
                    *(__half2*)(C16 + (size_t)(r + 8) * N + cidx) = __floats2half2_rn(v1.x, v1.y);
            }
        }
    }
}

// ---------------- small SGEMM (64x64 tile) for gat3, fp16 output -----------
__global__ void sgemm_kernel(const float* __restrict__ A,
                             const float* __restrict__ W,
                             __half* __restrict__ C16,
                             int M, int K, int Ncols) {
    __shared__ float As[16][64];
    __shared__ float Ws[16][64];
    const int tid = threadIdx.x;
    const int tx = tid & 15, ty = tid >> 4;
    const int m0 = blockIdx.y * 64, n0 = blockIdx.x * 64;
    const int ar = tid >> 2, ac = (tid & 3) * 4;
    const int wr = tid >> 4, wc = (tid & 15) * 4;
    float acc[4][4] = {};
    for (int k0 = 0; k0 < K; k0 += 16) {
        float4 av = make_float4(0.f, 0.f, 0.f, 0.f);
        if (m0 + ar < M)
            av = *(const float4*)(A + (size_t)(m0 + ar) * K + k0 + ac);
        As[ac + 0][ar] = av.x;
        As[ac + 1][ar] = av.y;
        As[ac + 2][ar] = av.z;
        As[ac + 3][ar] = av.w;
        *(float4*)&Ws[wr][wc] = *(const float4*)(W + (size_t)(k0 + wr) * Ncols + n0 + wc);
        __syncthreads();
#pragma unroll
        for (int kk = 0; kk < 16; kk++) {
            float4 a = *(const float4*)&As[kk][ty * 4];
            float4 b = *(const float4*)&Ws[kk][tx * 4];
            float am[4] = {a.x, a.y, a.z, a.w};
            float bm[4] = {b.x, b.y, b.z, b.w};
#pragma unroll
            for (int i = 0; i < 4; i++)
#pragma unroll
                for (int j = 0; j < 4; j++)
                    acc[i][j] += am[i] * bm[j];
        }
        __syncthreads();
    }
#pragma unroll
    for (int i = 0; i < 4; i++) {
        int m = m0 + ty * 4 + i;
        if (m >= M) break;
        __half2 h0 = __floats2half2_rn(acc[i][0], acc[i][1]);
        __half2 h1 = __floats2half2_rn(acc[i][2], acc[i][3]);
        __half2* p = (__half2*)(C16 + (size_t)m * Ncols + n0 + tx * 4);
        p[0] = h0; p[1] = h1;
    }
}

// ---------------- per-node attention scores (fp16 xh): warp per (n,h) ------
template <int H>
__global__ void attn_scores_kernel(const __half* __restrict__ xh,
                                   const float* __restrict__ a_src,
                                   const float* __restrict__ a_dst,
                                   float* __restrict__ ssrc,
                                   float* __restrict__ sdst) {
    int warp = (blockIdx.x * blockDim.x + threadIdx.x) >> 5;
    int lane = threadIdx.x & 31;
    if (warp >= NN * H) return;
    int n = warp / H, h = warp % H;
    const __half2* row = (const __half2*)(xh + (size_t)n * H * 64 + h * 64);
    float2 x = __half22float2(row[lane]);
    float2 as = *(const float2*)(a_src + h * 64 + lane * 2);
    float2 ad = *(const float2*)(a_dst + h * 64 + lane * 2);
    float ps = x.x * as.x + x.y * as.y;
    float pd = x.x * ad.x + x.y * ad.y;
#pragma unroll
    for (int o = 16; o; o >>= 1) {
        ps += __shfl_xor_sync(0xffffffffu, ps, o);
        pd += __shfl_xor_sync(0xffffffffu, pd, o);
    }
    if (lane == 0) { ssrc[warp] = ps; sdst[warp] = pd; }
}

// ---------------- fused CSR aggregate, 4-edge unrolled batches -------------
// MODE 0: concat + bias + ELU, output tf32-rounded (feeds GAT2 GEMM)
// MODE 1: mean2 + bias + ELU (feeds fp32 sgemm, no rounding)
// MODE 2: plain + bias (final output)
template <int H, int MODE>
__global__ void __launch_bounds__(128)
gat_aggregate(const int* __restrict__ offs,
              const int* __restrict__ csr,
              const __half* __restrict__ xh,
              const float* __restrict__ ssrc,
              const float* __restrict__ sdst,
              const float* __restrict__ bias,
              float* __restrict__ out) {
    const int TPN = H * 16;          // threads per node (4 halves each)
    const int NPB = 128 / TPN;       // nodes per block
    const int t = threadIdx.x % TPN;
    const int n = blockIdx.x * NPB + threadIdx.x / TPN;
    const int h = t >> 4;

    const float sd = sdst[n * H + h];
    const int beg = offs[n], end = offs[n + 1];

    float4 acc = make_float4(0.f, 0.f, 0.f, 0.f);
    float z = 0.f;

    int i = beg;
    for (; i + 3 < end; i += 4) {
        int s0 = __ldg(&csr[i]);
        int s1 = __ldg(&csr[i + 1]);
        int s2 = __ldg(&csr[i + 2]);
        int s3 = __ldg(&csr[i + 3]);
        float v0 = __ldg(&ssrc[s0 * H + h]);
        float v1 = __ldg(&ssrc[s1 * H + h]);
        float v2 = __ldg(&ssrc[s2 * H + h]);
        float v3 = __ldg(&ssrc[s3 * H + h]);
        uint2 u0 = *(const uint2*)(xh + (size_t)s0 * (H * 64) + t * 4);
        uint2 u1 = *(const uint2*)(xh + (size_t)s1 * (H * 64) + t * 4);
        uint2 u2 = *(const uint2*)(xh + (size_t)s2 * (H * 64) + t * 4);
        uint2 u3 = *(const uint2*)(xh + (size_t)s3 * (H * 64) + t * 4);

        v0 += sd; v0 = v0 > 0.f ? v0 : 0.2f * v0; float e0 = __expf(v0);
        v1 += sd; v1 = v1 > 0.f ? v1 : 0.2f * v1; float e1 = __expf(v1);
        v2 += sd; v2 = v2 > 0.f ? v2 : 0.2f * v2; float e2 = __expf(v2);
        v3 += sd; v3 = v3 > 0.f ? v3 : 0.2f * v3; float e3 = __expf(v3);

        float2 a0 = __half22float2(*(const __half2*)&u0.x);
        float2 b0 = __half22float2(*(const __half2*)&u0.y);
        float2 a1 = __half22float2(*(const __half2*)&u1.x);
        float2 b1 = __half22float2(*(const __half2*)&u1.y);
        float2 a2 = __half22float2(*(const __half2*)&u2.x);
        float2 b2 = __half22float2(*(const __half2*)&u2.y);
        float2 a3 = __half22float2(*(const __half2*)&u3.x);
        float2 b3 = __half22float2(*(const __half2*)&u3.y);

        acc.x += e0 * a0.x + e1 * a1.x + e2 * a2.x + e3 * a3.x;
        acc.y += e0 * a0.y + e1 * a1.y + e2 * a2.y + e3 * a3.y;
        acc.z += e0 * b0.x + e1 * b1.x + e2 * b2.x + e3 * b3.x;
        acc.w += e0 * b0.y + e1 * b1.y + e2 * b2.y + e3 * b3.y;
        z += (e0 + e1) + (e2 + e3);
    }
    for (; i < end; i++) {
        int src = __ldg(&csr[i]);
        float v = __ldg(&ssrc[src * H + h]) + sd;
        v = v > 0.f ? v : 0.2f * v;
        float e = __expf(v);
        uint2 u = *(const uint2*)(xh + (size_t)src * (H * 64) + t * 4);
        float2 f0 = __half22float2(*(const __half2*)&u.x);
        float2 f1 = __half22float2(*(const __half2*)&u.y);
        acc.x += e * f0.x;
        acc.y += e * f0.y;
        acc.z += e * f1.x;
        acc.w += e * f1.y;
        z += e;
    }

    float inv = 1.f / z;
    acc.x *= inv; acc.y *= inv; acc.z *= inv; acc.w *= inv;

    if constexpr (MODE == 0) {
        float4 bb = *(const float4*)(bias + t * 4);
        float4 v;
        v.x = acc.x + bb.x; v.y = acc.y + bb.y;
        v.z = acc.z + bb.z; v.w = acc.w + bb.w;
        v.x = v.x > 0.f ? v.x : expm1f(v.x);
        v.y = v.y > 0.f ? v.y : expm1f(v.y);
        v.z = v.z > 0.f ? v.z : expm1f(v.z);
        v.w = v.w > 0.f ? v.w : expm1f(v.w);
        v.x = f2tf_f(v.x); v.y = f2tf_f(v.y);
        v.z = f2tf_f(v.z); v.w = f2tf_f(v.w);
        *(float4*)(out + (size_t)n * 256 + t * 4) = v;
    } else if constexpr (MODE == 1) {
        float4 o;
        o.x = __shfl_xor_sync(0xffffffffu, acc.x, 16);
        o.y = __shfl_xor_sync(0xffffffffu, acc.y, 16);
        o.z = __shfl_xor_sync(0xffffffffu, acc.z, 16);
        o.w = __shfl_xor_sync(0xffffffffu, acc.w, 16);
        if (h == 0) {
            float4 bb = *(const float4*)(bias + t * 4);
            float4 v;
            v.x = 0.5f * (acc.x + o.x) + bb.x;
            v.y = 0.5f * (acc.y + o.y) + bb.y;
            v.z = 0.5f * (acc.z + o.z) + bb.z;
            v.w = 0.5f * (acc.w + o.w) + bb.w;
            v.x = v.x > 0.f ? v.x : expm1f(v.x);
            v.y = v.y > 0.f ? v.y : expm1f(v.y);
            v.z = v.z > 0.f ? v.z : expm1f(v.z);
            v.w = v.w > 0.f ? v.w : expm1f(v.w);
            *(float4*)(out + (size_t)n * 64 + t * 4) = v;
        }
    } else {
        float4 bb = *(const float4*)(bias + t * 4);
        float4 v;
        v.x = acc.x + bb.x; v.y = acc.y + bb.y;
        v.z = acc.z + bb.z; v.w = acc.w + bb.w;
        *(float4*)(out + (size_t)n * 64 + t * 4) = v;
    }
}

// ---------------------------------------------------------------------------
#define GEMM_SMEM 65536

static inline void run_tf32(const float* A, const float* W, const float* bias,
                            float* C, __half* C16, int M, int K, int N, int act) {
    dim3 grid(N / 128, (M + 127) / 128);
    tf32_gemm_kernel<<<grid, 256, GEMM_SMEM>>>(A, W, bias, C, C16, M, K, N, act);
}

extern "C" void kernel_launch(void* const* d_in, const int* in_sizes, int n_in,
                              void* d_out, int out_size) {
    const float* x    = (const float*)d_in[0];
    const int*   ei   = (const int*)d_in[1];
    const float* w1   = (const float*)d_in[2];
    const float* b1   = (const float*)d_in[3];
    const float* w2   = (const float*)d_in[4];
    const float* b2   = (const float*)d_in[5];
    const float* g1w  = (const float*)d_in[6];
    const float* g1as = (const float*)d_in[7];
    const float* g1ad = (const float*)d_in[8];
    const float* g1b  = (const float*)d_in[9];
    const float* g2w  = (const float*)d_in[10];
    const float* g2as = (const float*)d_in[11];
    const float* g2ad = (const float*)d_in[12];
    const float* g2b  = (const float*)d_in[13];
    const float* g3w  = (const float*)d_in[14];
    const float* g3as = (const float*)d_in[15];
    const float* g3ad = (const float*)d_in[16];
    const float* g3b  = (const float*)d_in[17];
    float* out = (float*)d_out;

    float *bufA, *bufB, *bufC, *ssrc, *sdst;
    float *w1r, *w2r, *g1wr, *g2wr;
    __half* xh16;
    int *deg, *offs, *cursor, *csr;
    cudaGetSymbolAddress((void**)&bufA, g_bufA);
    cudaGetSymbolAddress((void**)&bufB, g_bufB);
    cudaGetSymbolAddress((void**)&bufC, g_bufC);
    cudaGetSymbolAddress((void**)&xh16, g_xh16);
    cudaGetSymbolAddress((void**)&ssrc, g_ssrc);
    cudaGetSymbolAddress((void**)&sdst, g_sdst);
    cudaGetSymbolAddress((void**)&deg, g_deg);
    cudaGetSymbolAddress((void**)&offs, g_offs);
    cudaGetSymbolAddress((void**)&cursor, g_cursor);
    cudaGetSymbolAddress((void**)&csr, g_csr);
    cudaGetSymbolAddress((void**)&w1r, g_w1r);
    cudaGetSymbolAddress((void**)&w2r, g_w2r);
    cudaGetSymbolAddress((void**)&g1wr, g_g1wr);
    cudaGetSymbolAddress((void**)&g2wr, g_g2wr);

    cudaFuncSetAttribute(tf32_gemm_kernel,
                         cudaFuncAttributeMaxDynamicSharedMemorySize, GEMM_SMEM);

    const int M = NN;

    // ---------------- tf32 pre-rounding (x + weights) -----------------------
    round_tf32_vec4<<<(NN * 256 / 4 + 255) / 256, 256>>>(x, bufA, NN * 256 / 4);
    round_tf32_vec4<<<(256 * 128 / 4 + 255) / 256, 256>>>(w1, w1r, 256 * 128 / 4);
    round_tf32_vec4<<<(128 * 128 / 4 + 255) / 256, 256>>>(w2, w2r, 128 * 128 / 4);
    round_tf32_vec4<<<(128 * 256 / 4 + 255) / 256, 256>>>(g1w, g1wr, 128 * 256 / 4);
    round_tf32_vec4<<<(256 * 128 / 4 + 255) / 256, 256>>>(g2w, g2wr, 256 * 128 / 4);

    // ---------------- CSR build (once, reused by all 3 GAT layers) ----------
    cudaMemsetAsync(deg, 0, NN * sizeof(int));
    deg_count_kernel<<<(NT + 255) / 256, 256>>>(ei, deg);
    scan_kernel<<<1, 1024>>>(deg, offs, cursor);
    csr_fill_kernel<<<(NT + 255) / 256, 256>>>(ei, cursor, csr);

    // ---------------- MLP (tf32 path, C stores tf32-rounded) ----------------
    run_tf32(bufA, w1r, b1, bufC, nullptr, M, 256, 128, 1);   // h0
    run_tf32(bufC, w2r, b2, bufB, nullptr, M, 128, 128, 1);   // h1

    // ---------------- GAT1: H=4, D=64, concat, in=bufB(128) -----------------
    run_tf32(bufB, g1wr, nullptr, nullptr, xh16, M, 128, 256, 0);  // xh1 fp16
    attn_scores_kernel<4><<<(NN * 4 * 32 + 255) / 256, 256>>>(xh16, g1as, g1ad, ssrc, sdst);
    gat_aggregate<4, 0><<<NN / 2, 128>>>(offs, csr, xh16, ssrc, sdst, g1b, bufC);

    // ---------------- GAT2: H=2, D=64, mean, in=bufC(256) -------------------
    run_tf32(bufC, g2wr, nullptr, nullptr, xh16, M, 256, 128, 0);  // xh2 fp16
    attn_scores_kernel<2><<<(NN * 2 * 32 + 255) / 256, 256>>>(xh16, g2as, g2ad, ssrc, sdst);
    gat_aggregate<2, 1><<<NN / 4, 128>>>(offs, csr, xh16, ssrc, sdst, g2b, bufA);

    // ---------------- GAT3: H=1, D=64, mean(identity), in=bufA(64) ----------
    {
        dim3 grid(64 / 64, (M + 63) / 64);
        sgemm_kernel<<<grid, 256>>>(bufA, g3w, xh16, M, 64, 64);  // xh3 fp16
    }
    attn_scores_kernel<1><<<(NN * 1 * 32 + 255) / 256, 256>>>(xh16, g3as, g3ad, ssrc, sdst);
    gat_aggregate<1, 2><<<NN / 8, 128>>>(offs, csr, xh16, ssrc, sdst, g3b, out);
}

// round 14
// speedup vs baseline: 1.1573x; 1.0790x over previous
#include <cuda_runtime.h>
#include <cuda_fp16.h>
#include <math.h>
#include <stdint.h>

#define NN 50000
#define NE 800000
#define NT (NN + NE)   // edges incl. self loops

// ---------------- scratch (static device globals; allowed) ----------------
__device__ float  g_bufA[NN * 64];      // fp32 h3 (GAT2 output)
__device__ __half g_h16a[NN * 256];     // 25.6 MB
__device__ __half g_h16b[NN * 256];
__device__ __half g_h16c[NN * 256];
__device__ float  g_ssrc[NN * 4];
__device__ float  g_sdst[NN * 4];
__device__ int    g_deg[NN];
__device__ int    g_offs[NN + 1];
__device__ int    g_cursor[NN];
__device__ int    g_csr[NT];
// fp16 weight copies
__device__ __half g_w1h[256 * 128];
__device__ __half g_w2h[128 * 128];
__device__ __half g_g1wh[128 * 256];
__device__ __half g_g2wh[256 * 128];

// ---------------- fp32 -> fp16 convert -------------------------------------
__global__ void f32_to_f16_vec4(const float* __restrict__ in,
                                __half* __restrict__ out, int n4) {
    int i = blockIdx.x * blockDim.x + threadIdx.x;
    if (i >= n4) return;
    float4 v = ((const float4*)in)[i];
    uint2 u;
    *(__half2*)&u.x = __floats2half2_rn(v.x, v.y);
    *(__half2*)&u.y = __floats2half2_rn(v.z, v.w);
    ((uint2*)out)[i] = u;
}

// ---------------- CSR build ------------------------------------------------
__global__ void deg_count_kernel(const int* __restrict__ ei, int* __restrict__ deg) {
    int e = blockIdx.x * blockDim.x + threadIdx.x;
    if (e >= NT) return;
    int d = (e < NE) ? ei[NE + e] : (e - NE);
    atomicAdd(&deg[d], 1);
}

__global__ void scan_kernel(const int* __restrict__ deg,
                            int* __restrict__ offs,
                            int* __restrict__ cursor) {
    __shared__ int sh[1024];
    const int tid = threadIdx.x;
    const int CH = (NN + 1023) / 1024;   // 49
    const int base = tid * CH;
    int s = 0;
    for (int i = 0; i < CH; i++) {
        int idx = base + i;
        if (idx < NN) s += deg[idx];
    }
    sh[tid] = s;
    __syncthreads();
    int mine = s;
    for (int off = 1; off < 1024; off <<= 1) {
        int t2 = (tid >= off) ? sh[tid - off] : 0;
        __syncthreads();
        sh[tid] += t2;
        __syncthreads();
    }
    int run = sh[tid] - mine;   // exclusive prefix
    for (int i = 0; i < CH; i++) {
        int idx = base + i;
        if (idx < NN) {
            offs[idx] = run;
            cursor[idx] = run;
            run += deg[idx];
        }
    }
    if (tid == 1023) offs[NN] = run;
}

__global__ void csr_fill_kernel(const int* __restrict__ ei,
                                int* __restrict__ cursor,
                                int* __restrict__ csr) {
    int e = blockIdx.x * blockDim.x + threadIdx.x;
    if (e >= NT) return;
    int s, d;
    if (e < NE) { s = ei[e]; d = ei[NE + e]; }
    else        { s = d = e - NE; }
    int pos = atomicAdd(&cursor[d], 1);
    csr[pos] = s;
}

// ---------------- fp16 tensor-core GEMM (m16n8k16), cp.async 2-stage -------
// C16 = act(A[M,K] @ W[K,N] + bias), fp32 accumulate, fp16 in/out.
// smem: A rows padded to 40 halves (80B), B rows padded to 136 halves (272B).
__device__ __forceinline__ void mma16(float* c, const uint32_t* a, const uint32_t* b) {
    asm volatile(
        "mma.sync.aligned.m16n8k16.row.col.f32.f16.f16.f32 "
        "{%0,%1,%2,%3}, {%4,%5,%6,%7}, {%8,%9}, {%0,%1,%2,%3};"
        : "+f"(c[0]), "+f"(c[1]), "+f"(c[2]), "+f"(c[3])
        : "r"(a[0]), "r"(a[1]), "r"(a[2]), "r"(a[3]), "r"(b[0]), "r"(b[1]));
}
__device__ __forceinline__ void ldsm4(uint32_t* r, uint32_t addr) {
    asm volatile("ldmatrix.sync.aligned.m8n8.x4.shared.b16 {%0,%1,%2,%3}, [%4];"
                 : "=r"(r[0]), "=r"(r[1]), "=r"(r[2]), "=r"(r[3]) : "r"(addr));
}
__device__ __forceinline__ void ldsm4t(uint32_t* r, uint32_t addr) {
    asm volatile("ldmatrix.sync.aligned.m8n8.x4.trans.shared.b16 {%0,%1,%2,%3}, [%4];"
                 : "=r"(r[0]), "=r"(r[1]), "=r"(r[2]), "=r"(r[3]) : "r"(addr));
}
__device__ __forceinline__ void cp16(uint32_t daddr, const void* src, int nbytes) {
    asm volatile("cp.async.cg.shared.global [%0], [%1], 16, %2;"
                 :: "r"(daddr), "l"(src), "r"(nbytes) : "memory");
}

#define SA_STRIDE 40      // halves per A smem row
#define SB_STRIDE 136     // halves per B smem row
#define SA_STAGE  (128 * SA_STRIDE)   // 5120 halves
#define SB_STAGE  (32 * SB_STRIDE)    // 4352 halves
#define HGEMM_SMEM ((2 * SA_STAGE + 2 * SB_STAGE) * 2)  // bytes = 37888

__global__ void __launch_bounds__(256, 2)
hgemm_kernel(const __half* __restrict__ A, const __half* __restrict__ W,
             const float* __restrict__ bias, __half* __restrict__ C16,
             int M, int K, int N, int act) {
    extern __shared__ __half sm[];
    const int tid = threadIdx.x;
    const int lane = tid & 31, warp = tid >> 5;
    const int wm = warp & 3, wn = warp >> 2;    // 4 warps along M, 2 along N
    const int gid = lane >> 2, tig = lane & 3;
    const int m0 = blockIdx.y * 128, n0 = blockIdx.x * 128;

    float acc[2][8][4];
#pragma unroll
    for (int i = 0; i < 2; i++)
#pragma unroll
        for (int j = 0; j < 8; j++)
#pragma unroll
            for (int q = 0; q < 4; q++) acc[i][j][q] = 0.f;

    const int nIter = K >> 5;

    auto load_stage = [&](int s, int k0) {
        __half* sA = sm + s * SA_STAGE;
        __half* sB = sm + 2 * SA_STAGE + s * SB_STAGE;
#pragma unroll
        for (int i = 0; i < 2; i++) {          // A: 128 rows x 32 halves
            int idx = i * 256 + tid;
            int row = idx >> 2, c = (idx & 3) * 8;
            int ok = (m0 + row < M);
            cp16((uint32_t)__cvta_generic_to_shared(sA + row * SA_STRIDE + c),
                 A + (size_t)(m0 + (ok ? row : 0)) * K + k0 + c, ok ? 16 : 0);
        }
#pragma unroll
        for (int i = 0; i < 2; i++) {          // B: 32 rows x 128 halves
            int idx = i * 256 + tid;
            int k = idx >> 4, c = (idx & 15) * 8;
            cp16((uint32_t)__cvta_generic_to_shared(sB + k * SB_STRIDE + c),
                 W + (size_t)(k0 + k) * N + n0 + c, 16);
        }
    };

    load_stage(0, 0);
    asm volatile("cp.async.commit_group;" ::: "memory");

    for (int it = 0; it < nIter; it++) {
        if (it + 1 < nIter) load_stage((it + 1) & 1, (it + 1) << 5);
        asm volatile("cp.async.commit_group;" ::: "memory");
        asm volatile("cp.async.wait_group 1;" ::: "memory");
        __syncthreads();

        const __half* sA = sm + (it & 1) * SA_STAGE;
        const __half* sB = sm + 2 * SA_STAGE + (it & 1) * SB_STAGE;

        // ldmatrix lane coords (shared by A and B forms)
        const int l8 = lane & 7;
        const int lh = (lane >> 3) & 1;   // +8 row/col selector
        const int lq = lane >> 4;         // +8 second-half selector

#pragma unroll
        for (int kk = 0; kk < 32; kk += 16) {
            uint32_t a[2][4];
#pragma unroll
            for (int mt = 0; mt < 2; mt++) {
                int row = wm * 32 + mt * 16 + l8 + lh * 8;
                int col = kk + lq * 8;
                ldsm4(a[mt], (uint32_t)__cvta_generic_to_shared(sA + row * SA_STRIDE + col));
            }
            uint32_t b[8][2];
#pragma unroll
            for (int p = 0; p < 4; p++) {
                int k = kk + l8 + lh * 8;
                int n = wn * 64 + p * 16 + lq * 8;
                uint32_t r[4];
                ldsm4t(r, (uint32_t)__cvta_generic_to_shared(sB + k * SB_STRIDE + n));
                b[2 * p][0] = r[0]; b[2 * p][1] = r[1];
                b[2 * p + 1][0] = r[2]; b[2 * p + 1][1] = r[3];
            }
#pragma unroll
            for (int nt = 0; nt < 8; nt++) {
                mma16(acc[0][nt], a[0], b[nt]);
                mma16(acc[1][nt], a[1], b[nt]);
            }
        }
        __syncthreads();
    }

    // --- epilogue: bias + optional relu, fp16 stores ---
#pragma unroll
    for (int mt = 0; mt < 2; mt++) {
        int r = m0 + wm * 32 + mt * 16 + gid;
#pragma unroll
        for (int nt = 0; nt < 8; nt++) {
            int cidx = n0 + wn * 64 + nt * 8 + tig * 2;
            float bv0 = 0.f, bv1 = 0.f;
            if (bias) { bv0 = bias[cidx]; bv1 = bias[cidx + 1]; }
            float2 v0, v1;
            v0.x = acc[mt][nt][0] + bv0;
            v0.y = acc[mt][nt][1] + bv1;
            v1.x = acc[mt][nt][2] + bv0;
            v1.y = acc[mt][nt][3] + bv1;
            if (act) {
                v0.x = fmaxf(v0.x, 0.f); v0.y = fmaxf(v0.y, 0.f);
                v1.x = fmaxf(v1.x, 0.f); v1.y = fmaxf(v1.y, 0.f);
            }
            if (r < M)
                *(__half2*)(C16 + (size_t)r * N + cidx) = __floats2half2_rn(v0.x, v0.y);
            if (r + 8 < M)
                *(__half2*)(C16 + (size_t)(r + 8) * N + cidx) = __floats2half2_rn(v1.x, v1.y);
        }
    }
}

// ---------------- small SGEMM (64x64 tile) for gat3, fp32 in / fp16 out ----
__global__ void sgemm_kernel(const float* __restrict__ A,
                             const float* __restrict__ W,
                             __half* __restrict__ C16,
                             int M, int K, int Ncols) {
    __shared__ float As[16][64];
    __shared__ float Ws[16][64];
    const int tid = threadIdx.x;
    const int tx = tid & 15, ty = tid >> 4;
    const int m0 = blockIdx.y * 64, n0 = blockIdx.x * 64;
    const int ar = tid >> 2, ac = (tid & 3) * 4;
    const int wr = tid >> 4, wc = (tid & 15) * 4;
    float acc[4][4] = {};
    for (int k0 = 0; k0 < K; k0 += 16) {
        float4 av = make_float4(0.f, 0.f, 0.f, 0.f);
        if (m0 + ar < M)
            av = *(const float4*)(A + (size_t)(m0 + ar) * K + k0 + ac);
        As[ac + 0][ar] = av.x;
        As[ac + 1][ar] = av.y;
        As[ac + 2][ar] = av.z;
        As[ac + 3][ar] = av.w;
        *(float4*)&Ws[wr][wc] = *(const float4*)(W + (size_t)(k0 + wr) * Ncols + n0 + wc);
        __syncthreads();
#pragma unroll
        for (int kk = 0; kk < 16; kk++) {
            float4 a = *(const float4*)&As[kk][ty * 4];
            float4 b = *(const float4*)&Ws[kk][tx * 4];
            float am[4] = {a.x, a.y, a.z, a.w};
            float bm[4] = {b.x, b.y, b.z, b.w};
#pragma unroll
            for (int i = 0; i < 4; i++)
#pragma unroll
                for (int j = 0; j < 4; j++)
                    acc[i][j] += am[i] * bm[j];
        }
        __syncthreads();
    }
#pragma unroll
    for (int i = 0; i < 4; i++) {
        int m = m0 + ty * 4 + i;
        if (m >= M) break;
        __half2 h0 = __floats2half2_rn(acc[i][0], acc[i][1]);
        __half2 h1 = __floats2half2_rn(acc[i][2], acc[i][3]);
        __half2* p = (__half2*)(C16 + (size_t)m * Ncols + n0 + tx * 4);
        p[0] = h0; p[1] = h1;
    }
}

// ---------------- per-node attention scores (fp16 xh): warp per (n,h) ------
template <int H>
__global__ void attn_scores_kernel(const __half* __restrict__ xh,
                                   const float* __restrict__ a_src,
                                   const float* __restrict__ a_dst,
                                   float* __restrict__ ssrc,
                                   float* __restrict__ sdst) {
    int warp = (blockIdx.x * blockDim.x + threadIdx.x) >> 5;
    int lane = threadIdx.x & 31;
    if (warp >= NN * H) return;
    int n = warp / H, h = warp % H;
    const __half2* row = (const __half2*)(xh + (size_t)n * H * 64 + h * 64);
    float2 x = __half22float2(row[lane]);
    float2 as = *(const float2*)(a_src + h * 64 + lane * 2);
    float2 ad = *(const float2*)(a_dst + h * 64 + lane * 2);
    float ps = x.x * as.x + x.y * as.y;
    float pd = x.x * ad.x + x.y * ad.y;
#pragma unroll
    for (int o = 16; o; o >>= 1) {
        ps += __shfl_xor_sync(0xffffffffu, ps, o);
        pd += __shfl_xor_sync(0xffffffffu, pd, o);
    }
    if (lane == 0) { ssrc[warp] = ps; sdst[warp] = pd; }
}

// ---------------- fused CSR aggregate, 4-edge unrolled batches -------------
// MODE 0: concat + bias + ELU -> __half out (feeds GAT2 GEMM)
// MODE 1: mean2 + bias + ELU  -> float out (feeds fp32 sgemm)
// MODE 2: plain + bias        -> float out (final)
template <int H, int MODE>
__global__ void __launch_bounds__(128)
gat_aggregate(const int* __restrict__ offs,
              const int* __restrict__ csr,
              const __half* __restrict__ xh,
              const float* __restrict__ ssrc,
              const float* __restrict__ sdst,
              const float* __restrict__ bias,
              void* __restrict__ out_raw) {
    const int TPN = H * 16;          // threads per node (4 halves each)
    const int NPB = 128 / TPN;       // nodes per block
    const int t = threadIdx.x % TPN;
    const int n = blockIdx.x * NPB + threadIdx.x / TPN;
    const int h = t >> 4;

    const float sd = sdst[n * H + h];
    const int beg = offs[n], end = offs[n + 1];

    float4 acc = make_float4(0.f, 0.f, 0.f, 0.f);
    float z = 0.f;

    int i = beg;
    for (; i + 3 < end; i += 4) {
        int s0 = __ldg(&csr[i]);
        int s1 = __ldg(&csr[i + 1]);
        int s2 = __ldg(&csr[i + 2]);
        int s3 = __ldg(&csr[i + 3]);
        float v0 = __ldg(&ssrc[s0 * H + h]);
        float v1 = __ldg(&ssrc[s1 * H + h]);
        float v2 = __ldg(&ssrc[s2 * H + h]);
        float v3 = __ldg(&ssrc[s3 * H + h]);
        uint2 u0 = *(const uint2*)(xh + (size_t)s0 * (H * 64) + t * 4);
        uint2 u1 = *(const uint2*)(xh + (size_t)s1 * (H * 64) + t * 4);
        uint2 u2 = *(const uint2*)(xh + (size_t)s2 * (H * 64) + t * 4);
        uint2 u3 = *(const uint2*)(xh + (size_t)s3 * (H * 64) + t * 4);

        v0 += sd; v0 = v0 > 0.f ? v0 : 0.2f * v0; float e0 = __expf(v0);
        v1 += sd; v1 = v1 > 0.f ? v1 : 0.2f * v1; float e1 = __expf(v1);
        v2 += sd; v2 = v2 > 0.f ? v2 : 0.2f * v2; float e2 = __expf(v2);
        v3 += sd; v3 = v3 > 0.f ? v3 : 0.2f * v3; float e3 = __expf(v3);

        float2 a0 = __half22float2(*(const __half2*)&u0.x);
        float2 b0 = __half22float2(*(const __half2*)&u0.y);
        float2 a1 = __half22float2(*(const __half2*)&u1.x);
        float2 b1 = __half22float2(*(const __half2*)&u1.y);
        float2 a2 = __half22float2(*(const __half2*)&u2.x);
        float2 b2 = __half22float2(*(const __half2*)&u2.y);
        float2 a3 = __half22float2(*(const __half2*)&u3.x);
        float2 b3 = __half22float2(*(const __half2*)&u3.y);

        acc.x += e0 * a0.x + e1 * a1.x + e2 * a2.x + e3 * a3.x;
        acc.y += e0 * a0.y + e1 * a1.y + e2 * a2.y + e3 * a3.y;
        acc.z += e0 * b0.x + e1 * b1.x + e2 * b2.x + e3 * b3.x;
        acc.w += e0 * b0.y + e1 * b1.y + e2 * b2.y + e3 * b3.y;
        z += (e0 + e1) + (e2 + e3);
    }
    for (; i < end; i++) {
        int src = __ldg(&csr[i]);
        float v = __ldg(&ssrc[src * H + h]) + sd;
        v = v > 0.f ? v : 0.2f * v;
        float e = __expf(v);
        uint2 u = *(const uint2*)(xh + (size_t)src * (H * 64) + t * 4);
        float2 f0 = __half22float2(*(const __half2*)&u.x);
        float2 f1 = __half22float2(*(const __half2*)&u.y);
        acc.x += e * f0.x;
        acc.y += e * f0.y;
        acc.z += e * f1.x;
        acc.w += e * f1.y;
        z += e;
    }

    float inv = 1.f / z;
    acc.x *= inv; acc.y *= inv; acc.z *= inv; acc.w *= inv;

    if constexpr (MODE == 0) {
        __half* out = (__half*)out_raw;
        float4 bb = *(const float4*)(bias + t * 4);
        float4 v;
        v.x = acc.x + bb.x; v.y = acc.y + bb.y;
        v.z = acc.z + bb.z; v.w = acc.w + bb.w;
        v.x = v.x > 0.f ? v.x : expm1f(v.x);
        v.y = v.y > 0.f ? v.y : expm1f(v.y);
        v.z = v.z > 0.f ? v.z : expm1f(v.z);
        v.w = v.w > 0.f ? v.w : expm1f(v.w);
        uint2 u;
        *(__half2*)&u.x = __floats2half2_rn(v.x, v.y);
        *(__half2*)&u.y = __floats2half2_rn(v.z, v.w);
        *(uint2*)(out + (size_t)n * 256 + t * 4) = u;
    } else if constexpr (MODE == 1) {
        float* out = (float*)out_raw;
        float4 o;
        o.x = __shfl_xor_sync(0xffffffffu, acc.x, 16);
        o.y = __shfl_xor_sync(0xffffffffu, acc.y, 16);
        o.z = __shfl_xor_sync(0xffffffffu, acc.z, 16);
        o.w = __shfl_xor_sync(0xffffffffu, acc.w, 16);
        if (h == 0) {
            float4 bb = *(const float4*)(bias + t * 4);
            float4 v;
            v.x = 0.5f * (acc.x + o.x) + bb.x;
            v.y = 0.5f * (acc.y + o.y) + bb.y;
            v.z = 0.5f * (acc.z + o.z) + bb.z;
            v.w = 0.5f * (acc.w + o.w) + bb.w;
            v.x = v.x > 0.f ? v.x : expm1f(v.x);
            v.y = v.y > 0.f ? v.y : expm1f(v.y);
            v.z = v.z > 0.f ? v.z : expm1f(v.z);
            v.w = v.w > 0.f ? v.w : expm1f(v.w);
            *(float4*)(out + (size_t)n * 64 + t * 4) = v;
        }
    } else {
        float* out = (float*)out_raw;
        float4 bb = *(const float4*)(bias + t * 4);
        float4 v;
        v.x = acc.x + bb.x; v.y = acc.y + bb.y;
        v.z = acc.z + bb.z; v.w = acc.w + bb.w;
        *(float4*)(out + (size_t)n * 64 + t * 4) = v;
    }
}

// ---------------------------------------------------------------------------
static inline void run_hgemm(const __half* A, const __half* W, const float* bias,
                             __half* C16, int M, int K, int N, int act) {
    dim3 grid(N / 128, (M + 127) / 128);
    hgemm_kernel<<<grid, 256, HGEMM_SMEM>>>(A, W, bias, C16, M, K, N, act);
}

extern "C" void kernel_launch(void* const* d_in, const int* in_sizes, int n_in,
                              void* d_out, int out_size) {
    const float* x    = (const float*)d_in[0];
    const int*   ei   = (const int*)d_in[1];
    const float* w1   = (const float*)d_in[2];
    const float* b1   = (const float*)d_in[3];
    const float* w2   = (const float*)d_in[4];
    const float* b2   = (const float*)d_in[5];
    const float* g1w  = (const float*)d_in[6];
    const float* g1as = (const float*)d_in[7];
    const float* g1ad = (const float*)d_in[8];
    const float* g1b  = (const float*)d_in[9];
    const float* g2w  = (const float*)d_in[10];
    const float* g2as = (const float*)d_in[11];
    const float* g2ad = (const float*)d_in[12];
    const float* g2b  = (const float*)d_in[13];
    const float* g3w  = (const float*)d_in[14];
    const float* g3as = (const float*)d_in[15];
    const float* g3ad = (const float*)d_in[16];
    const float* g3b  = (const float*)d_in[17];
    float* out = (float*)d_out;

    float *bufA, *ssrc, *sdst;
    __half *h16a, *h16b, *h16c, *w1h, *w2h, *g1wh, *g2wh;
    int *deg, *offs, *cursor, *csr;
    cudaGetSymbolAddress((void**)&bufA, g_bufA);
    cudaGetSymbolAddress((void**)&h16a, g_h16a);
    cudaGetSymbolAddress((void**)&h16b, g_h16b);
    cudaGetSymbolAddress((void**)&h16c, g_h16c);
    cudaGetSymbolAddress((void**)&ssrc, g_ssrc);
    cudaGetSymbolAddress((void**)&sdst, g_sdst);
    cudaGetSymbolAddress((void**)&deg, g_deg);
    cudaGetSymbolAddress((void**)&offs, g_offs);
    cudaGetSymbolAddress((void**)&cursor, g_cursor);
    cudaGetSymbolAddress((void**)&csr, g_csr);
    cudaGetSymbolAddress((void**)&w1h, g_w1h);
    cudaGetSymbolAddress((void**)&w2h, g_w2h);
    cudaGetSymbolAddress((void**)&g1wh, g_g1wh);
    cudaGetSymbolAddress((void**)&g2wh, g_g2wh);

    const int M = NN;

    // ---------------- fp16 conversion (x + weights) -------------------------
    f32_to_f16_vec4<<<(NN * 256 / 4 + 255) / 256, 256>>>(x, h16a, NN * 256 / 4);
    f32_to_f16_vec4<<<(256 * 128 / 4 + 255) / 256, 256>>>(w1, w1h, 256 * 128 / 4);
    f32_to_f16_vec4<<<(128 * 128 / 4 + 255) / 256, 256>>>(w2, w2h, 128 * 128 / 4);
    f32_to_f16_vec4<<<(128 * 256 / 4 + 255) / 256, 256>>>(g1w, g1wh, 128 * 256 / 4);
    f32_to_f16_vec4<<<(256 * 128 / 4 + 255) / 256, 256>>>(g2w, g2wh, 256 * 128 / 4);

    // ---------------- CSR build (once, reused by all 3 GAT layers) ----------
    cudaMemsetAsync(deg, 0, NN * sizeof(int));
    deg_count_kernel<<<(NT + 255) / 256, 256>>>(ei, deg);
    scan_kernel<<<1, 1024>>>(deg, offs, cursor);
    csr_fill_kernel<<<(NT + 255) / 256, 256>>>(ei, cursor, csr);

    // ---------------- MLP ----------------
    run_hgemm(h16a, w1h, b1, h16b, M, 256, 128, 1);   // h0 -> b
    run_hgemm(h16b, w2h, b2, h16c, M, 128, 128, 1);   // h1 -> c

    // ---------------- GAT1: H=4, D=64, concat ------------------------------
    run_hgemm(h16c, g1wh, nullptr, h16a, M, 128, 256, 0);   // xh1 -> a
    attn_scores_kernel<4><<<(NN * 4 * 32 + 255) / 256, 256>>>(h16a, g1as, g1ad, ssrc, sdst);
    gat_aggregate<4, 0><<<NN / 2, 128>>>(offs, csr, h16a, ssrc, sdst, g1b, h16b);  // out1 -> b

    // ---------------- GAT2: H=2, D=64, mean --------------------------------
    run_hgemm(h16b, g2wh, nullptr, h16c, M, 256, 128, 0);   // xh2 -> c
    attn_scores_kernel<2><<<(NN * 2 * 32 + 255) / 256, 256>>>(h16c, g2as, g2ad, ssrc, sdst);
    gat_aggregate<2, 1><<<NN / 4, 128>>>(offs, csr, h16c, ssrc, sdst, g2b, bufA);  // h3 -> fp32

    // ---------------- GAT3: H=1, D=64 --------------------------------------
    {
        dim3 grid(1, (M + 63) / 64);
        sgemm_kernel<<<grid, 256>>>(bufA, g3w, h16a, M, 64, 64);   // xh3 -> a
    }
    attn_scores_kernel<1><<<(NN * 1 * 32 + 255) / 256, 256>>>(h16a, g3as, g3ad, ssrc, sdst);
    gat_aggregate<1, 2><<<NN / 8, 128>>>(offs, csr, h16a, ssrc, sdst, g3b, out);
}

// round 15
// speedup vs baseline: 1.2297x; 1.0625x over previous
#include <cuda_runtime.h>
#include <cuda_fp16.h>
#include <math.h>
#include <stdint.h>

#define NN 50000
#define NE 800000
#define NT (NN + NE)   // edges incl. self loops

// ---------------- scratch (static device globals; allowed) ----------------
__device__ float  g_bufA[NN * 64];      // fp32 h3 (GAT2 output)
__device__ __half g_h16a[NN * 256];     // 25.6 MB
__device__ __half g_h16b[NN * 256];
__device__ __half g_h16c[NN * 256];
__device__ float  g_ssrc[NN * 4];
__device__ float  g_sdst[NN * 4];
__device__ int    g_deg[NN];
__device__ int    g_offs[NN + 1];
__device__ int    g_cursor[NN];
__device__ int    g_csr[NT];
// fp16 weight copies
__device__ __half g_w1h[256 * 128];
__device__ __half g_w2h[128 * 128];
__device__ __half g_g1wh[128 * 256];
__device__ __half g_g2wh[256 * 128];

// ---------------- fp32 -> fp16 convert -------------------------------------
__global__ void f32_to_f16_vec4(const float* __restrict__ in,
                                __half* __restrict__ out, int n4) {
    int i = blockIdx.x * blockDim.x + threadIdx.x;
    if (i >= n4) return;
    float4 v = ((const float4*)in)[i];
    uint2 u;
    *(__half2*)&u.x = __floats2half2_rn(v.x, v.y);
    *(__half2*)&u.y = __floats2half2_rn(v.z, v.w);
    ((uint2*)out)[i] = u;
}

// ---------------- CSR build ------------------------------------------------
__global__ void deg_count_kernel(const int* __restrict__ ei, int* __restrict__ deg) {
    int e = blockIdx.x * blockDim.x + threadIdx.x;
    if (e >= NT) return;
    int d = (e < NE) ? ei[NE + e] : (e - NE);
    atomicAdd(&deg[d], 1);
}

__global__ void scan_kernel(const int* __restrict__ deg,
                            int* __restrict__ offs,
                            int* __restrict__ cursor) {
    __shared__ int sh[1024];
    const int tid = threadIdx.x;
    const int CH = (NN + 1023) / 1024;   // 49
    const int base = tid * CH;
    int s = 0;
    for (int i = 0; i < CH; i++) {
        int idx = base + i;
        if (idx < NN) s += deg[idx];
    }
    sh[tid] = s;
    __syncthreads();
    int mine = s;
    for (int off = 1; off < 1024; off <<= 1) {
        int t2 = (tid >= off) ? sh[tid - off] : 0;
        __syncthreads();
        sh[tid] += t2;
        __syncthreads();
    }
    int run = sh[tid] - mine;   // exclusive prefix
    for (int i = 0; i < CH; i++) {
        int idx = base + i;
        if (idx < NN) {
            offs[idx] = run;
            cursor[idx] = run;
            run += deg[idx];
        }
    }
    if (tid == 1023) offs[NN] = run;
}

__global__ void csr_fill_kernel(const int* __restrict__ ei,
                                int* __restrict__ cursor,
                                int* __restrict__ csr) {
    int e = blockIdx.x * blockDim.x + threadIdx.x;
    if (e >= NT) return;
    int s, d;
    if (e < NE) { s = ei[e]; d = ei[NE + e]; }
    else        { s = d = e - NE; }
    int pos = atomicAdd(&cursor[d], 1);
    csr[pos] = s;
}

// ---------------- fp16 tensor-core GEMM (m16n8k16), cp.async 2-stage -------
// C16 = act(A[M,K] @ W[K,N] + bias). If ssrc != null, also emits per-row
// attention scores ssrc/sdst (warp n-tile == one 64-wide head).
__device__ __forceinline__ void mma16(float* c, const uint32_t* a, const uint32_t* b) {
    asm volatile(
        "mma.sync.aligned.m16n8k16.row.col.f32.f16.f16.f32 "
        "{%0,%1,%2,%3}, {%4,%5,%6,%7}, {%8,%9}, {%0,%1,%2,%3};"
        : "+f"(c[0]), "+f"(c[1]), "+f"(c[2]), "+f"(c[3])
        : "r"(a[0]), "r"(a[1]), "r"(a[2]), "r"(a[3]), "r"(b[0]), "r"(b[1]));
}
__device__ __forceinline__ void ldsm4(uint32_t* r, uint32_t addr) {
    asm volatile("ldmatrix.sync.aligned.m8n8.x4.shared.b16 {%0,%1,%2,%3}, [%4];"
                 : "=r"(r[0]), "=r"(r[1]), "=r"(r[2]), "=r"(r[3]) : "r"(addr));
}
__device__ __forceinline__ void ldsm4t(uint32_t* r, uint32_t addr) {
    asm volatile("ldmatrix.sync.aligned.m8n8.x4.trans.shared.b16 {%0,%1,%2,%3}, [%4];"
                 : "=r"(r[0]), "=r"(r[1]), "=r"(r[2]), "=r"(r[3]) : "r"(addr));
}
__device__ __forceinline__ void cp16(uint32_t daddr, const void* src, int nbytes) {
    asm volatile("cp.async.cg.shared.global [%0], [%1], 16, %2;"
                 :: "r"(daddr), "l"(src), "r"(nbytes) : "memory");
}

#define SA_STRIDE 40      // halves per A smem row
#define SB_STRIDE 136     // halves per B smem row
#define SA_STAGE  (128 * SA_STRIDE)   // 5120 halves
#define SB_STAGE  (32 * SB_STRIDE)    // 4352 halves
#define HGEMM_SMEM ((2 * SA_STAGE + 2 * SB_STAGE) * 2)  // bytes = 37888

__global__ void __launch_bounds__(256, 2)
hgemm_kernel(const __half* __restrict__ A, const __half* __restrict__ W,
             const float* __restrict__ bias, __half* __restrict__ C16,
             int M, int K, int N, int act,
             const float* __restrict__ a_src, const float* __restrict__ a_dst,
             float* __restrict__ ssrc, float* __restrict__ sdst, int H) {
    extern __shared__ __half sm[];
    const int tid = threadIdx.x;
    const int lane = tid & 31, warp = tid >> 5;
    const int wm = warp & 3, wn = warp >> 2;    // 4 warps along M, 2 along N
    const int gid = lane >> 2, tig = lane & 3;
    const int m0 = blockIdx.y * 128, n0 = blockIdx.x * 128;

    float acc[2][8][4];
#pragma unroll
    for (int i = 0; i < 2; i++)
#pragma unroll
        for (int j = 0; j < 8; j++)
#pragma unroll
            for (int q = 0; q < 4; q++) acc[i][j][q] = 0.f;

    const int nIter = K >> 5;

    auto load_stage = [&](int s, int k0) {
        __half* sA = sm + s * SA_STAGE;
        __half* sB = sm + 2 * SA_STAGE + s * SB_STAGE;
#pragma unroll
        for (int i = 0; i < 2; i++) {          // A: 128 rows x 32 halves
            int idx = i * 256 + tid;
            int row = idx >> 2, c = (idx & 3) * 8;
            int ok = (m0 + row < M);
            cp16((uint32_t)__cvta_generic_to_shared(sA + row * SA_STRIDE + c),
                 A + (size_t)(m0 + (ok ? row : 0)) * K + k0 + c, ok ? 16 : 0);
        }
#pragma unroll
        for (int i = 0; i < 2; i++) {          // B: 32 rows x 128 halves
            int idx = i * 256 + tid;
            int k = idx >> 4, c = (idx & 15) * 8;
            cp16((uint32_t)__cvta_generic_to_shared(sB + k * SB_STRIDE + c),
                 W + (size_t)(k0 + k) * N + n0 + c, 16);
        }
    };

    load_stage(0, 0);
    asm volatile("cp.async.commit_group;" ::: "memory");

    for (int it = 0; it < nIter; it++) {
        if (it + 1 < nIter) load_stage((it + 1) & 1, (it + 1) << 5);
        asm volatile("cp.async.commit_group;" ::: "memory");
        asm volatile("cp.async.wait_group 1;" ::: "memory");
        __syncthreads();

        const __half* sA = sm + (it & 1) * SA_STAGE;
        const __half* sB = sm + 2 * SA_STAGE + (it & 1) * SB_STAGE;

        const int l8 = lane & 7;
        const int lh = (lane >> 3) & 1;
        const int lq = lane >> 4;

#pragma unroll
        for (int kk = 0; kk < 32; kk += 16) {
            uint32_t a[2][4];
#pragma unroll
            for (int mt = 0; mt < 2; mt++) {
                int row = wm * 32 + mt * 16 + l8 + lh * 8;
                int col = kk + lq * 8;
                ldsm4(a[mt], (uint32_t)__cvta_generic_to_shared(sA + row * SA_STRIDE + col));
            }
            uint32_t b[8][2];
#pragma unroll
            for (int p = 0; p < 4; p++) {
                int k = kk + l8 + lh * 8;
                int n = wn * 64 + p * 16 + lq * 8;
                uint32_t r[4];
                ldsm4t(r, (uint32_t)__cvta_generic_to_shared(sB + k * SB_STRIDE + n));
                b[2 * p][0] = r[0]; b[2 * p][1] = r[1];
                b[2 * p + 1][0] = r[2]; b[2 * p + 1][1] = r[3];
            }
#pragma unroll
            for (int nt = 0; nt < 8; nt++) {
                mma16(acc[0][nt], a[0], b[nt]);
                mma16(acc[1][nt], a[1], b[nt]);
            }
        }
        __syncthreads();
    }

    // --- epilogue: bias + optional relu, fp16 stores, fused attn scores ----
    const bool scores = (ssrc != nullptr);
    const int hidx = (n0 >> 6) + wn;    // 64-wide warp tile == one head
#pragma unroll
    for (int mt = 0; mt < 2; mt++) {
        int r = m0 + wm * 32 + mt * 16 + gid;
        float ps0 = 0.f, pd0 = 0.f, ps1 = 0.f, pd1 = 0.f;
#pragma unroll
        for (int nt = 0; nt < 8; nt++) {
            int cidx = n0 + wn * 64 + nt * 8 + tig * 2;
            float bv0 = 0.f, bv1 = 0.f;
            if (bias) { bv0 = bias[cidx]; bv1 = bias[cidx + 1]; }
            float2 v0, v1;
            v0.x = acc[mt][nt][0] + bv0;
            v0.y = acc[mt][nt][1] + bv1;
            v1.x = acc[mt][nt][2] + bv0;
            v1.y = acc[mt][nt][3] + bv1;
            if (act) {
                v0.x = fmaxf(v0.x, 0.f); v0.y = fmaxf(v0.y, 0.f);
                v1.x = fmaxf(v1.x, 0.f); v1.y = fmaxf(v1.y, 0.f);
            }
            if (scores) {
                int cl = hidx * 64 + nt * 8 + tig * 2;
                float as0 = __ldg(&a_src[cl]), as1 = __ldg(&a_src[cl + 1]);
                float ad0 = __ldg(&a_dst[cl]), ad1 = __ldg(&a_dst[cl + 1]);
                ps0 += v0.x * as0 + v0.y * as1;
                pd0 += v0.x * ad0 + v0.y * ad1;
                ps1 += v1.x * as0 + v1.y * as1;
                pd1 += v1.x * ad0 + v1.y * ad1;
            }
            if (r < M)
                *(__half2*)(C16 + (size_t)r * N + cidx) = __floats2half2_rn(v0.x, v0.y);
            if (r + 8 < M)
                *(__half2*)(C16 + (size_t)(r + 8) * N + cidx) = __floats2half2_rn(v1.x, v1.y);
        }
        if (scores) {
#pragma unroll
            for (int o = 1; o < 4; o <<= 1) {
                ps0 += __shfl_xor_sync(0xffffffffu, ps0, o);
                pd0 += __shfl_xor_sync(0xffffffffu, pd0, o);
                ps1 += __shfl_xor_sync(0xffffffffu, ps1, o);
                pd1 += __shfl_xor_sync(0xffffffffu, pd1, o);
            }
            if (tig == 0 && r < M)     { ssrc[r * H + hidx] = ps0; sdst[r * H + hidx] = pd0; }
            if (tig == 1 && r + 8 < M) { ssrc[(r + 8) * H + hidx] = ps1; sdst[(r + 8) * H + hidx] = pd1; }
        }
    }
}

// ---------------- small SGEMM (64x64) for gat3: fp16 out + fused scores ----
__global__ void sgemm_kernel(const float* __restrict__ A,
                             const float* __restrict__ W,
                             __half* __restrict__ C16,
                             int M, int K, int Ncols,
                             const float* __restrict__ a_src,
                             const float* __restrict__ a_dst,
                             float* __restrict__ ssrc, float* __restrict__ sdst) {
    __shared__ float As[16][64];
    __shared__ float Ws[16][64];
    const int tid = threadIdx.x;
    const int tx = tid & 15, ty = tid >> 4;
    const int m0 = blockIdx.y * 64, n0 = blockIdx.x * 64;
    const int ar = tid >> 2, ac = (tid & 3) * 4;
    const int wr = tid >> 4, wc = (tid & 15) * 4;
    float acc[4][4] = {};
    for (int k0 = 0; k0 < K; k0 += 16) {
        float4 av = make_float4(0.f, 0.f, 0.f, 0.f);
        if (m0 + ar < M)
            av = *(const float4*)(A + (size_t)(m0 + ar) * K + k0 + ac);
        As[ac + 0][ar] = av.x;
        As[ac + 1][ar] = av.y;
        As[ac + 2][ar] = av.z;
        As[ac + 3][ar] = av.w;
        *(float4*)&Ws[wr][wc] = *(const float4*)(W + (size_t)(k0 + wr) * Ncols + n0 + wc);
        __syncthreads();
#pragma unroll
        for (int kk = 0; kk < 16; kk++) {
            float4 a = *(const float4*)&As[kk][ty * 4];
            float4 b = *(const float4*)&Ws[kk][tx * 4];
            float am[4] = {a.x, a.y, a.z, a.w};
            float bm[4] = {b.x, b.y, b.z, b.w};
#pragma unroll
            for (int i = 0; i < 4; i++)
#pragma unroll
                for (int j = 0; j < 4; j++)
                    acc[i][j] += am[i] * bm[j];
        }
        __syncthreads();
    }
    float as[4], ad[4];
#pragma unroll
    for (int j = 0; j < 4; j++) {
        as[j] = __ldg(&a_src[n0 + tx * 4 + j]);
        ad[j] = __ldg(&a_dst[n0 + tx * 4 + j]);
    }
#pragma unroll
    for (int i = 0; i < 4; i++) {
        int m = m0 + ty * 4 + i;
        float ps = acc[i][0] * as[0] + acc[i][1] * as[1] + acc[i][2] * as[2] + acc[i][3] * as[3];
        float pd = acc[i][0] * ad[0] + acc[i][1] * ad[1] + acc[i][2] * ad[2] + acc[i][3] * ad[3];
#pragma unroll
        for (int o = 1; o < 16; o <<= 1) {
            ps += __shfl_xor_sync(0xffffffffu, ps, o);
            pd += __shfl_xor_sync(0xffffffffu, pd, o);
        }
        if (m < M) {
            if (tx == 0) { ssrc[m] = ps; sdst[m] = pd; }
            __half2 h0 = __floats2half2_rn(acc[i][0], acc[i][1]);
            __half2 h1 = __floats2half2_rn(acc[i][2], acc[i][3]);
            __half2* p = (__half2*)(C16 + (size_t)m * Ncols + n0 + tx * 4);
            p[0] = h0; p[1] = h1;
        }
    }
}

// ---------------- fused CSR aggregate, 4-edge unrolled batches -------------
// MODE 0: concat + bias + ELU -> __half out (feeds GAT2 GEMM)
// MODE 1: mean2 + bias + ELU  -> float out (feeds fp32 sgemm)
// MODE 2: plain + bias        -> float out (final)
template <int H, int MODE>
__global__ void __launch_bounds__(128)
gat_aggregate(const int* __restrict__ offs,
              const int* __restrict__ csr,
              const __half* __restrict__ xh,
              const float* __restrict__ ssrc,
              const float* __restrict__ sdst,
              const float* __restrict__ bias,
              void* __restrict__ out_raw) {
    const int TPN = H * 16;          // threads per node (4 halves each)
    const int NPB = 128 / TPN;       // nodes per block
    const int t = threadIdx.x % TPN;
    const int n = blockIdx.x * NPB + threadIdx.x / TPN;
    const int h = t >> 4;

    const float sd = sdst[n * H + h];
    const int beg = offs[n], end = offs[n + 1];

    float4 acc = make_float4(0.f, 0.f, 0.f, 0.f);
    float z = 0.f;

    int i = beg;
    for (; i + 3 < end; i += 4) {
        int s0 = __ldg(&csr[i]);
        int s1 = __ldg(&csr[i + 1]);
        int s2 = __ldg(&csr[i + 2]);
        int s3 = __ldg(&csr[i + 3]);
        float v0 = __ldg(&ssrc[s0 * H + h]);
        float v1 = __ldg(&ssrc[s1 * H + h]);
        float v2 = __ldg(&ssrc[s2 * H + h]);
        float v3 = __ldg(&ssrc[s3 * H + h]);
        uint2 u0 = *(const uint2*)(xh + (size_t)s0 * (H * 64) + t * 4);
        uint2 u1 = *(const uint2*)(xh + (size_t)s1 * (H * 64) + t * 4);
        uint2 u2 = *(const uint2*)(xh + (size_t)s2 * (H * 64) + t * 4);
        uint2 u3 = *(const uint2*)(xh + (size_t)s3 * (H * 64) + t * 4);

        v0 += sd; v0 = v0 > 0.f ? v0 : 0.2f * v0; float e0 = __expf(v0);
        v1 += sd; v1 = v1 > 0.f ? v1 : 0.2f * v1; float e1 = __expf(v1);
        v2 += sd; v2 = v2 > 0.f ? v2 : 0.2f * v2; float e2 = __expf(v2);
        v3 += sd; v3 = v3 > 0.f ? v3 : 0.2f * v3; float e3 = __expf(v3);

        float2 a0 = __half22float2(*(const __half2*)&u0.x);
        float2 b0 = __half22float2(*(const __half2*)&u0.y);
        float2 a1 = __half22float2(*(const __half2*)&u1.x);
        float2 b1 = __half22float2(*(const __half2*)&u1.y);
        float2 a2 = __half22float2(*(const __half2*)&u2.x);
        float2 b2 = __half22float2(*(const __half2*)&u2.y);
        float2 a3 = __half22float2(*(const __half2*)&u3.x);
        float2 b3 = __half22float2(*(const __half2*)&u3.y);

        acc.x += e0 * a0.x + e1 * a1.x + e2 * a2.x + e3 * a3.x;
        acc.y += e0 * a0.y + e1 * a1.y + e2 * a2.y + e3 * a3.y;
        acc.z += e0 * b0.x + e1 * b1.x + e2 * b2.x + e3 * b3.x;
        acc.w += e0 * b0.y + e1 * b1.y + e2 * b2.y + e3 * b3.y;
        z += (e0 + e1) + (e2 + e3);
    }
    for (; i < end; i++) {
        int src = __ldg(&csr[i]);
        float v = __ldg(&ssrc[src * H + h]) + sd;
        v = v > 0.f ? v : 0.2f * v;
        float e = __expf(v);
        uint2 u = *(const uint2*)(xh + (size_t)src * (H * 64) + t * 4);
        float2 f0 = __half22float2(*(const __half2*)&u.x);
        float2 f1 = __half22float2(*(const __half2*)&u.y);
        acc.x += e * f0.x;
        acc.y += e * f0.y;
        acc.z += e * f1.x;
        acc.w += e * f1.y;
        z += e;
    }

    float inv = 1.f / z;
    acc.x *= inv; acc.y *= inv; acc.z *= inv; acc.w *= inv;

    if constexpr (MODE == 0) {
        __half* out = (__half*)out_raw;
        float4 bb = *(const float4*)(bias + t * 4);
        float4 v;
        v.x = acc.x + bb.x; v.y = acc.y + bb.y;
        v.z = acc.z + bb.z; v.w = acc.w + bb.w;
        v.x = v.x > 0.f ? v.x : expm1f(v.x);
        v.y = v.y > 0.f ? v.y : expm1f(v.y);
        v.z = v.z > 0.f ? v.z : expm1f(v.z);
        v.w = v.w > 0.f ? v.w : expm1f(v.w);
        uint2 u;
        *(__half2*)&u.x = __floats2half2_rn(v.x, v.y);
        *(__half2*)&u.y = __floats2half2_rn(v.z, v.w);
        *(uint2*)(out + (size_t)n * 256 + t * 4) = u;
    } else if constexpr (MODE == 1) {
        float* out = (float*)out_raw;
        float4 o;
        o.x = __shfl_xor_sync(0xffffffffu, acc.x, 16);
        o.y = __shfl_xor_sync(0xffffffffu, acc.y, 16);
        o.z = __shfl_xor_sync(0xffffffffu, acc.z, 16);
        o.w = __shfl_xor_sync(0xffffffffu, acc.w, 16);
        if (h == 0) {
            float4 bb = *(const float4*)(bias + t * 4);
            float4 v;
            v.x = 0.5f * (acc.x + o.x) + bb.x;
            v.y = 0.5f * (acc.y + o.y) + bb.y;
            v.z = 0.5f * (acc.z + o.z) + bb.z;
            v.w = 0.5f * (acc.w + o.w) + bb.w;
            v.x = v.x > 0.f ? v.x : expm1f(v.x);
            v.y = v.y > 0.f ? v.y : expm1f(v.y);
            v.z = v.z > 0.f ? v.z : expm1f(v.z);
            v.w = v.w > 0.f ? v.w : expm1f(v.w);
            *(float4*)(out + (size_t)n * 64 + t * 4) = v;
        }
    } else {
        float* out = (float*)out_raw;
        float4 bb = *(const float4*)(bias + t * 4);
        float4 v;
        v.x = acc.x + bb.x; v.y = acc.y + bb.y;
        v.z = acc.z + bb.z; v.w = acc.w + bb.w;
        *(float4*)(out + (size_t)n * 64 + t * 4) = v;
    }
}

// ---------------------------------------------------------------------------
static inline void run_hgemm(const __half* A, const __half* W, const float* bias,
                             __half* C16, int M, int K, int N, int act,
                             const float* as = nullptr, const float* ad = nullptr,
                             float* ssrc = nullptr, float* sdst = nullptr, int H = 1) {
    dim3 grid(N / 128, (M + 127) / 128);
    hgemm_kernel<<<grid, 256, HGEMM_SMEM>>>(A, W, bias, C16, M, K, N, act,
                                            as, ad, ssrc, sdst, H);
}

extern "C" void kernel_launch(void* const* d_in, const int* in_sizes, int n_in,
                              void* d_out, int out_size) {
    const float* x    = (const float*)d_in[0];
    const int*   ei   = (const int*)d_in[1];
    const float* w1   = (const float*)d_in[2];
    const float* b1   = (const float*)d_in[3];
    const float* w2   = (const float*)d_in[4];
    const float* b2   = (const float*)d_in[5];
    const float* g1w  = (const float*)d_in[6];
    const float* g1as = (const float*)d_in[7];
    const float* g1ad = (const float*)d_in[8];
    const float* g1b  = (const float*)d_in[9];
    const float* g2w  = (const float*)d_in[10];
    const float* g2as = (const float*)d_in[11];
    const float* g2ad = (const float*)d_in[12];
    const float* g2b  = (const float*)d_in[13];
    const float* g3w  = (const float*)d_in[14];
    const float* g3as = (const float*)d_in[15];
    const float* g3ad = (const float*)d_in[16];
    const float* g3b  = (const float*)d_in[17];
    float* out = (float*)d_out;

    float *bufA, *ssrc, *sdst;
    __half *h16a, *h16b, *h16c, *w1h, *w2h, *g1wh, *g2wh;
    int *deg, *offs, *cursor, *csr;
    cudaGetSymbolAddress((void**)&bufA, g_bufA);
    cudaGetSymbolAddress((void**)&h16a, g_h16a);
    cudaGetSymbolAddress((void**)&h16b, g_h16b);
    cudaGetSymbolAddress((void**)&h16c, g_h16c);
    cudaGetSymbolAddress((void**)&ssrc, g_ssrc);
    cudaGetSymbolAddress((void**)&sdst, g_sdst);
    cudaGetSymbolAddress((void**)&deg, g_deg);
    cudaGetSymbolAddress((void**)&offs, g_offs);
    cudaGetSymbolAddress((void**)&cursor, g_cursor);
    cudaGetSymbolAddress((void**)&csr, g_csr);
    cudaGetSymbolAddress((void**)&w1h, g_w1h);
    cudaGetSymbolAddress((void**)&w2h, g_w2h);
    cudaGetSymbolAddress((void**)&g1wh, g_g1wh);
    cudaGetSymbolAddress((void**)&g2wh, g_g2wh);

    const int M = NN;

    // ---------------- fp16 conversion (x + weights) -------------------------
    f32_to_f16_vec4<<<(NN * 256 / 4 + 255) / 256, 256>>>(x, h16a, NN * 256 / 4);
    f32_to_f16_vec4<<<(256 * 128 / 4 + 255) / 256, 256>>>(w1, w1h, 256 * 128 / 4);
    f32_to_f16_vec4<<<(128 * 128 / 4 + 255) / 256, 256>>>(w2, w2h, 128 * 128 / 4);
    f32_to_f16_vec4<<<(128 * 256 / 4 + 255) / 256, 256>>>(g1w, g1wh, 128 * 256 / 4);
    f32_to_f16_vec4<<<(256 * 128 / 4 + 255) / 256, 256>>>(g2w, g2wh, 256 * 128 / 4);

    // ---------------- CSR build (once, reused by all 3 GAT layers) ----------
    cudaMemsetAsync(deg, 0, NN * sizeof(int));
    deg_count_kernel<<<(NT + 255) / 256, 256>>>(ei, deg);
    scan_kernel<<<1, 1024>>>(deg, offs, cursor);
    csr_fill_kernel<<<(NT + 255) / 256, 256>>>(ei, cursor, csr);

    // ---------------- MLP ----------------
    run_hgemm(h16a, w1h, b1, h16b, M, 256, 128, 1);   // h0 -> b
    run_hgemm(h16b, w2h, b2, h16c, M, 128, 128, 1);   // h1 -> c

    // ---------------- GAT1: H=4, D=64, concat (scores fused in GEMM) --------
    run_hgemm(h16c, g1wh, nullptr, h16a, M, 128, 256, 0,
              g1as, g1ad, ssrc, sdst, 4);                       // xh1 -> a
    gat_aggregate<4, 0><<<NN / 2, 128>>>(offs, csr, h16a, ssrc, sdst, g1b, h16b);

    // ---------------- GAT2: H=2, D=64, mean --------------------------------
    run_hgemm(h16b, g2wh, nullptr, h16c, M, 256, 128, 0,
              g2as, g2ad, ssrc, sdst, 2);                       // xh2 -> c
    gat_aggregate<2, 1><<<NN / 4, 128>>>(offs, csr, h16c, ssrc, sdst, g2b, bufA);

    // ---------------- GAT3: H=1, D=64 --------------------------------------
    {
        dim3 grid(1, (M + 63) / 64);
        sgemm_kernel<<<grid, 256>>>(bufA, g3w, h16a, M, 64, 64,
                                    g3as, g3ad, ssrc, sdst);    // xh3 -> a
    }
    gat_aggregate<1, 2><<<NN / 8, 128>>>(offs, csr, h16a, ssrc, sdst, g3b, out);
}

// round 16
// speedup vs baseline: 1.3285x; 1.0803x over previous
#include <cuda_runtime.h>
#include <cuda_fp16.h>
#include <math.h>
#include <stdint.h>

#define NN 50000
#define NE 800000
#define NT (NN + NE)   // edges incl. self loops

// ---------------- scratch (static device globals; allowed) ----------------
__device__ float  g_bufA[NN * 64];      // fp32 h3 (GAT2 output)
__device__ __half g_h16a[NN * 256];     // 25.6 MB
__device__ __half g_h16b[NN * 256];
__device__ __half g_h16c[NN * 256];
__device__ float  g_ssrc[NN * 4];
__device__ float  g_sdst[NN * 4];
__device__ int    g_deg[NN];
__device__ int    g_offs[NN + 1];
__device__ int    g_cursor[NN];
__device__ int    g_csr[NT];
// fp16 weight copies
__device__ __half g_w1h[256 * 128];
__device__ __half g_w2h[128 * 128];
__device__ __half g_g1wh[128 * 256];
__device__ __half g_g2wh[256 * 128];

// ---------------- fp32 -> fp16 convert -------------------------------------
__global__ void f32_to_f16_vec4(const float* __restrict__ in,
                                __half* __restrict__ out, int n4) {
    int i = blockIdx.x * blockDim.x + threadIdx.x;
    if (i >= n4) return;
    float4 v = ((const float4*)in)[i];
    uint2 u;
    *(__half2*)&u.x = __floats2half2_rn(v.x, v.y);
    *(__half2*)&u.y = __floats2half2_rn(v.z, v.w);
    ((uint2*)out)[i] = u;
}

// ---------------- CSR build ------------------------------------------------
__global__ void deg_count_kernel(const int* __restrict__ ei, int* __restrict__ deg) {
    int e = blockIdx.x * blockDim.x + threadIdx.x;
    if (e >= NT) return;
    int d = (e < NE) ? ei[NE + e] : (e - NE);
    atomicAdd(&deg[d], 1);
}

__global__ void scan_kernel(const int* __restrict__ deg,
                            int* __restrict__ offs,
                            int* __restrict__ cursor) {
    __shared__ int sh[1024];
    const int tid = threadIdx.x;
    const int CH = (NN + 1023) / 1024;   // 49
    const int base = tid * CH;
    int s = 0;
    for (int i = 0; i < CH; i++) {
        int idx = base + i;
        if (idx < NN) s += deg[idx];
    }
    sh[tid] = s;
    __syncthreads();
    int mine = s;
    for (int off = 1; off < 1024; off <<= 1) {
        int t2 = (tid >= off) ? sh[tid - off] : 0;
        __syncthreads();
        sh[tid] += t2;
        __syncthreads();
    }
    int run = sh[tid] - mine;   // exclusive prefix
    for (int i = 0; i < CH; i++) {
        int idx = base + i;
        if (idx < NN) {
            offs[idx] = run;
            cursor[idx] = run;
            run += deg[idx];
        }
    }
    if (tid == 1023) offs[NN] = run;
}

__global__ void csr_fill_kernel(const int* __restrict__ ei,
                                int* __restrict__ cursor,
                                int* __restrict__ csr) {
    int e = blockIdx.x * blockDim.x + threadIdx.x;
    if (e >= NT) return;
    int s, d;
    if (e < NE) { s = ei[e]; d = ei[NE + e]; }
    else        { s = d = e - NE; }
    int pos = atomicAdd(&cursor[d], 1);
    csr[pos] = s;
}

// ---------------- fp16 tensor-core GEMM (m16n8k16), cp.async 2-stage -------
__device__ __forceinline__ void mma16(float* c, const uint32_t* a, const uint32_t* b) {
    asm volatile(
        "mma.sync.aligned.m16n8k16.row.col.f32.f16.f16.f32 "
        "{%0,%1,%2,%3}, {%4,%5,%6,%7}, {%8,%9}, {%0,%1,%2,%3};"
        : "+f"(c[0]), "+f"(c[1]), "+f"(c[2]), "+f"(c[3])
        : "r"(a[0]), "r"(a[1]), "r"(a[2]), "r"(a[3]), "r"(b[0]), "r"(b[1]));
}
__device__ __forceinline__ void ldsm4(uint32_t* r, uint32_t addr) {
    asm volatile("ldmatrix.sync.aligned.m8n8.x4.shared.b16 {%0,%1,%2,%3}, [%4];"
                 : "=r"(r[0]), "=r"(r[1]), "=r"(r[2]), "=r"(r[3]) : "r"(addr));
}
__device__ __forceinline__ void ldsm4t(uint32_t* r, uint32_t addr) {
    asm volatile("ldmatrix.sync.aligned.m8n8.x4.trans.shared.b16 {%0,%1,%2,%3}, [%4];"
                 : "=r"(r[0]), "=r"(r[1]), "=r"(r[2]), "=r"(r[3]) : "r"(addr));
}
__device__ __forceinline__ void cp16(uint32_t daddr, const void* src, int nbytes) {
    asm volatile("cp.async.cg.shared.global [%0], [%1], 16, %2;"
                 :: "r"(daddr), "l"(src), "r"(nbytes) : "memory");
}

#define SA_STRIDE 40      // halves per A smem row
#define SB_STRIDE 136     // halves per B smem row
#define SA_STAGE  (128 * SA_STRIDE)   // 5120 halves
#define SB_STAGE  (32 * SB_STRIDE)    // 4352 halves
#define HGEMM_SMEM ((2 * SA_STAGE + 2 * SB_STAGE) * 2)  // bytes = 37888

__global__ void __launch_bounds__(256, 2)
hgemm_kernel(const __half* __restrict__ A, const __half* __restrict__ W,
             const float* __restrict__ bias, __half* __restrict__ C16,
             int M, int K, int N, int act,
             const float* __restrict__ a_src, const float* __restrict__ a_dst,
             float* __restrict__ ssrc, float* __restrict__ sdst, int H) {
    extern __shared__ __half sm[];
    const int tid = threadIdx.x;
    const int lane = tid & 31, warp = tid >> 5;
    const int wm = warp & 3, wn = warp >> 2;    // 4 warps along M, 2 along N
    const int gid = lane >> 2, tig = lane & 3;
    const int m0 = blockIdx.y * 128, n0 = blockIdx.x * 128;

    float acc[2][8][4];
#pragma unroll
    for (int i = 0; i < 2; i++)
#pragma unroll
        for (int j = 0; j < 8; j++)
#pragma unroll
            for (int q = 0; q < 4; q++) acc[i][j][q] = 0.f;

    const int nIter = K >> 5;

    auto load_stage = [&](int s, int k0) {
        __half* sA = sm + s * SA_STAGE;
        __half* sB = sm + 2 * SA_STAGE + s * SB_STAGE;
#pragma unroll
        for (int i = 0; i < 2; i++) {          // A: 128 rows x 32 halves
            int idx = i * 256 + tid;
            int row = idx >> 2, c = (idx & 3) * 8;
            int ok = (m0 + row < M);
            cp16((uint32_t)__cvta_generic_to_shared(sA + row * SA_STRIDE + c),
                 A + (size_t)(m0 + (ok ? row : 0)) * K + k0 + c, ok ? 16 : 0);
        }
#pragma unroll
        for (int i = 0; i < 2; i++) {          // B: 32 rows x 128 halves
            int idx = i * 256 + tid;
            int k = idx >> 4, c = (idx & 15) * 8;
            cp16((uint32_t)__cvta_generic_to_shared(sB + k * SB_STRIDE + c),
                 W + (size_t)(k0 + k) * N + n0 + c, 16);
        }
    };

    load_stage(0, 0);
    asm volatile("cp.async.commit_group;" ::: "memory");

    for (int it = 0; it < nIter; it++) {
        if (it + 1 < nIter) load_stage((it + 1) & 1, (it + 1) << 5);
        asm volatile("cp.async.commit_group;" ::: "memory");
        asm volatile("cp.async.wait_group 1;" ::: "memory");
        __syncthreads();

        const __half* sA = sm + (it & 1) * SA_STAGE;
        const __half* sB = sm + 2 * SA_STAGE + (it & 1) * SB_STAGE;

        const int l8 = lane & 7;
        const int lh = (lane >> 3) & 1;
        const int lq = lane >> 4;

#pragma unroll
        for (int kk = 0; kk < 32; kk += 16) {
            uint32_t a[2][4];
#pragma unroll
            for (int mt = 0; mt < 2; mt++) {
                int row = wm * 32 + mt * 16 + l8 + lh * 8;
                int col = kk + lq * 8;
                ldsm4(a[mt], (uint32_t)__cvta_generic_to_shared(sA + row * SA_STRIDE + col));
            }
            uint32_t b[8][2];
#pragma unroll
            for (int p = 0; p < 4; p++) {
                int k = kk + l8 + lh * 8;
                int n = wn * 64 + p * 16 + lq * 8;
                uint32_t r[4];
                ldsm4t(r, (uint32_t)__cvta_generic_to_shared(sB + k * SB_STRIDE + n));
                b[2 * p][0] = r[0]; b[2 * p][1] = r[1];
                b[2 * p + 1][0] = r[2]; b[2 * p + 1][1] = r[3];
            }
#pragma unroll
            for (int nt = 0; nt < 8; nt++) {
                mma16(acc[0][nt], a[0], b[nt]);
                mma16(acc[1][nt], a[1], b[nt]);
            }
        }
        __syncthreads();
    }

    // --- epilogue: bias + optional relu, fp16 stores, fused attn scores ----
    const bool scores = (ssrc != nullptr);
    const int hidx = (n0 >> 6) + wn;    // 64-wide warp tile == one head
#pragma unroll
    for (int mt = 0; mt < 2; mt++) {
        int r = m0 + wm * 32 + mt * 16 + gid;
        float ps0 = 0.f, pd0 = 0.f, ps1 = 0.f, pd1 = 0.f;
#pragma unroll
        for (int nt = 0; nt < 8; nt++) {
            int cidx = n0 + wn * 64 + nt * 8 + tig * 2;
            float bv0 = 0.f, bv1 = 0.f;
            if (bias) { bv0 = bias[cidx]; bv1 = bias[cidx + 1]; }
            float2 v0, v1;
            v0.x = acc[mt][nt][0] + bv0;
            v0.y = acc[mt][nt][1] + bv1;
            v1.x = acc[mt][nt][2] + bv0;
            v1.y = acc[mt][nt][3] + bv1;
            if (act) {
                v0.x = fmaxf(v0.x, 0.f); v0.y = fmaxf(v0.y, 0.f);
                v1.x = fmaxf(v1.x, 0.f); v1.y = fmaxf(v1.y, 0.f);
            }
            if (scores) {
                int cl = hidx * 64 + nt * 8 + tig * 2;
                float as0 = __ldg(&a_src[cl]), as1 = __ldg(&a_src[cl + 1]);
                float ad0 = __ldg(&a_dst[cl]), ad1 = __ldg(&a_dst[cl + 1]);
                ps0 += v0.x * as0 + v0.y * as1;
                pd0 += v0.x * ad0 + v0.y * ad1;
                ps1 += v1.x * as0 + v1.y * as1;
                pd1 += v1.x * ad0 + v1.y * ad1;
            }
            if (r < M)
                *(__half2*)(C16 + (size_t)r * N + cidx) = __floats2half2_rn(v0.x, v0.y);
            if (r + 8 < M)
                *(__half2*)(C16 + (size_t)(r + 8) * N + cidx) = __floats2half2_rn(v1.x, v1.y);
        }
        if (scores) {
#pragma unroll
            for (int o = 1; o < 4; o <<= 1) {
                ps0 += __shfl_xor_sync(0xffffffffu, ps0, o);
                pd0 += __shfl_xor_sync(0xffffffffu, pd0, o);
                ps1 += __shfl_xor_sync(0xffffffffu, ps1, o);
                pd1 += __shfl_xor_sync(0xffffffffu, pd1, o);
            }
            if (tig == 0 && r < M)     { ssrc[r * H + hidx] = ps0; sdst[r * H + hidx] = pd0; }
            if (tig == 1 && r + 8 < M) { ssrc[(r + 8) * H + hidx] = ps1; sdst[(r + 8) * H + hidx] = pd1; }
        }
    }
}

// ---------------- small SGEMM (64x64) for gat3: fp16 out + fused scores ----
__global__ void sgemm_kernel(const float* __restrict__ A,
                             const float* __restrict__ W,
                             __half* __restrict__ C16,
                             int M, int K, int Ncols,
                             const float* __restrict__ a_src,
                             const float* __restrict__ a_dst,
                             float* __restrict__ ssrc, float* __restrict__ sdst) {
    __shared__ float As[16][64];
    __shared__ float Ws[16][64];
    const int tid = threadIdx.x;
    const int tx = tid & 15, ty = tid >> 4;
    const int m0 = blockIdx.y * 64, n0 = blockIdx.x * 64;
    const int ar = tid >> 2, ac = (tid & 3) * 4;
    const int wr = tid >> 4, wc = (tid & 15) * 4;
    float acc[4][4] = {};
    for (int k0 = 0; k0 < K; k0 += 16) {
        float4 av = make_float4(0.f, 0.f, 0.f, 0.f);
        if (m0 + ar < M)
            av = *(const float4*)(A + (size_t)(m0 + ar) * K + k0 + ac);
        As[ac + 0][ar] = av.x;
        As[ac + 1][ar] = av.y;
        As[ac + 2][ar] = av.z;
        As[ac + 3][ar] = av.w;
        *(float4*)&Ws[wr][wc] = *(const float4*)(W + (size_t)(k0 + wr) * Ncols + n0 + wc);
        __syncthreads();
#pragma unroll
        for (int kk = 0; kk < 16; kk++) {
            float4 a = *(const float4*)&As[kk][ty * 4];
            float4 b = *(const float4*)&Ws[kk][tx * 4];
            float am[4] = {a.x, a.y, a.z, a.w};
            float bm[4] = {b.x, b.y, b.z, b.w};
#pragma unroll
            for (int i = 0; i < 4; i++)
#pragma unroll
                for (int j = 0; j < 4; j++)
                    acc[i][j] += am[i] * bm[j];
        }
        __syncthreads();
    }
    float as[4], ad[4];
#pragma unroll
    for (int j = 0; j < 4; j++) {
        as[j] = __ldg(&a_src[n0 + tx * 4 + j]);
        ad[j] = __ldg(&a_dst[n0 + tx * 4 + j]);
    }
#pragma unroll
    for (int i = 0; i < 4; i++) {
        int m = m0 + ty * 4 + i;
        float ps = acc[i][0] * as[0] + acc[i][1] * as[1] + acc[i][2] * as[2] + acc[i][3] * as[3];
        float pd = acc[i][0] * ad[0] + acc[i][1] * ad[1] + acc[i][2] * ad[2] + acc[i][3] * ad[3];
#pragma unroll
        for (int o = 1; o < 16; o <<= 1) {
            ps += __shfl_xor_sync(0xffffffffu, ps, o);
            pd += __shfl_xor_sync(0xffffffffu, pd, o);
        }
        if (m < M) {
            if (tx == 0) { ssrc[m] = ps; sdst[m] = pd; }
            __half2 h0 = __floats2half2_rn(acc[i][0], acc[i][1]);
            __half2 h1 = __floats2half2_rn(acc[i][2], acc[i][3]);
            __half2* p = (__half2*)(C16 + (size_t)m * Ncols + n0 + tx * 4);
            p[0] = h0; p[1] = h1;
        }
    }
}

// ---------------- fused CSR aggregate: uint4/thread, TPN = 8*H -------------
// MODE 0: concat + bias + ELU -> __half out (feeds GAT2 GEMM)
// MODE 1: mean2 + bias + ELU  -> float out (feeds fp32 sgemm)
// MODE 2: plain + bias        -> float out (final)
template <int H, int MODE>
__global__ void __launch_bounds__(256)
gat_aggregate(const int* __restrict__ offs,
              const int* __restrict__ csr,
              const __half* __restrict__ xh,
              const float* __restrict__ ssrc,
              const float* __restrict__ sdst,
              const float* __restrict__ bias,
              void* __restrict__ out_raw) {
    const int TPN = H * 8;           // threads per node (8 halves each)
    const int NPB = 256 / TPN;       // nodes per block
    const int t = threadIdx.x % TPN;
    const int n = blockIdx.x * NPB + threadIdx.x / TPN;
    if (n >= NN) return;
    const int h = t >> 3;            // head index (8 threads per head)

    const float sd = sdst[n * H + h];
    const int beg = offs[n], end = offs[n + 1];

    float acc[8] = {};
    float z = 0.f;

    auto accum = [&](uint4 u, float e) {
        float2 f0 = __half22float2(*(const __half2*)&u.x);
        float2 f1 = __half22float2(*(const __half2*)&u.y);
        float2 f2 = __half22float2(*(const __half2*)&u.z);
        float2 f3 = __half22float2(*(const __half2*)&u.w);
        acc[0] += e * f0.x; acc[1] += e * f0.y;
        acc[2] += e * f1.x; acc[3] += e * f1.y;
        acc[4] += e * f2.x; acc[5] += e * f2.y;
        acc[6] += e * f3.x; acc[7] += e * f3.y;
    };

    int i = beg;
    for (; i + 3 < end; i += 4) {
        int s0 = __ldg(&csr[i]);
        int s1 = __ldg(&csr[i + 1]);
        int s2 = __ldg(&csr[i + 2]);
        int s3 = __ldg(&csr[i + 3]);
        float v0 = __ldg(&ssrc[s0 * H + h]);
        float v1 = __ldg(&ssrc[s1 * H + h]);
        float v2 = __ldg(&ssrc[s2 * H + h]);
        float v3 = __ldg(&ssrc[s3 * H + h]);
        uint4 u0 = *(const uint4*)(xh + (size_t)s0 * (H * 64) + t * 8);
        uint4 u1 = *(const uint4*)(xh + (size_t)s1 * (H * 64) + t * 8);
        uint4 u2 = *(const uint4*)(xh + (size_t)s2 * (H * 64) + t * 8);
        uint4 u3 = *(const uint4*)(xh + (size_t)s3 * (H * 64) + t * 8);

        v0 += sd; v0 = v0 > 0.f ? v0 : 0.2f * v0; float e0 = __expf(v0);
        v1 += sd; v1 = v1 > 0.f ? v1 : 0.2f * v1; float e1 = __expf(v1);
        v2 += sd; v2 = v2 > 0.f ? v2 : 0.2f * v2; float e2 = __expf(v2);
        v3 += sd; v3 = v3 > 0.f ? v3 : 0.2f * v3; float e3 = __expf(v3);

        accum(u0, e0); accum(u1, e1); accum(u2, e2); accum(u3, e3);
        z += (e0 + e1) + (e2 + e3);
    }
    for (; i < end; i++) {
        int src = __ldg(&csr[i]);
        float v = __ldg(&ssrc[src * H + h]) + sd;
        v = v > 0.f ? v : 0.2f * v;
        float e = __expf(v);
        uint4 u = *(const uint4*)(xh + (size_t)src * (H * 64) + t * 8);
        accum(u, e);
        z += e;
    }

    float inv = 1.f / z;
#pragma unroll
    for (int q = 0; q < 8; q++) acc[q] *= inv;

    if constexpr (MODE == 0) {
        __half* out = (__half*)out_raw;
        float b0[4], b1[4];
        *(float4*)b0 = *(const float4*)(bias + t * 8);
        *(float4*)b1 = *(const float4*)(bias + t * 8 + 4);
        float v[8];
#pragma unroll
        for (int q = 0; q < 4; q++) { v[q] = acc[q] + b0[q]; v[q + 4] = acc[q + 4] + b1[q]; }
#pragma unroll
        for (int q = 0; q < 8; q++) v[q] = v[q] > 0.f ? v[q] : expm1f(v[q]);
        uint4 u;
        *(__half2*)&u.x = __floats2half2_rn(v[0], v[1]);
        *(__half2*)&u.y = __floats2half2_rn(v[2], v[3]);
        *(__half2*)&u.z = __floats2half2_rn(v[4], v[5]);
        *(__half2*)&u.w = __floats2half2_rn(v[6], v[7]);
        *(uint4*)(out + (size_t)n * 256 + t * 8) = u;
    } else if constexpr (MODE == 1) {
        // TPN == 16: threads t<8 hold head0, t>=8 hold head1 (same channels)
        float* out = (float*)out_raw;
        float o[8];
#pragma unroll
        for (int q = 0; q < 8; q++) o[q] = __shfl_xor_sync(0xffffffffu, acc[q], 8);
        if (h == 0) {
            float b0[4], b1[4];
            *(float4*)b0 = *(const float4*)(bias + t * 8);
            *(float4*)b1 = *(const float4*)(bias + t * 8 + 4);
            float v[8];
#pragma unroll
            for (int q = 0; q < 4; q++) {
                v[q] = 0.5f * (acc[q] + o[q]) + b0[q];
                v[q + 4] = 0.5f * (acc[q + 4] + o[q + 4]) + b1[q];
            }
#pragma unroll
            for (int q = 0; q < 8; q++) v[q] = v[q] > 0.f ? v[q] : expm1f(v[q]);
            *(float4*)(out + (size_t)n * 64 + t * 8) = *(float4*)v;
            *(float4*)(out + (size_t)n * 64 + t * 8 + 4) = *(float4*)(v + 4);
        }
    } else {
        float* out = (float*)out_raw;
        float b0[4], b1[4];
        *(float4*)b0 = *(const float4*)(bias + t * 8);
        *(float4*)b1 = *(const float4*)(bias + t * 8 + 4);
        float v[8];
#pragma unroll
        for (int q = 0; q < 4; q++) { v[q] = acc[q] + b0[q]; v[q + 4] = acc[q + 4] + b1[q]; }
        *(float4*)(out + (size_t)n * 64 + t * 8) = *(float4*)v;
        *(float4*)(out + (size_t)n * 64 + t * 8 + 4) = *(float4*)(v + 4);
    }
}

// ---------------------------------------------------------------------------
static inline void run_hgemm(const __half* A, const __half* W, const float* bias,
                             __half* C16, int M, int K, int N, int act,
                             const float* as = nullptr, const float* ad = nullptr,
                             float* ssrc = nullptr, float* sdst = nullptr, int H = 1) {
    dim3 grid(N / 128, (M + 127) / 128);
    hgemm_kernel<<<grid, 256, HGEMM_SMEM>>>(A, W, bias, C16, M, K, N, act,
                                            as, ad, ssrc, sdst, H);
}

extern "C" void kernel_launch(void* const* d_in, const int* in_sizes, int n_in,
                              void* d_out, int out_size) {
    const float* x    = (const float*)d_in[0];
    const int*   ei   = (const int*)d_in[1];
    const float* w1   = (const float*)d_in[2];
    const float* b1   = (const float*)d_in[3];
    const float* w2   = (const float*)d_in[4];
    const float* b2   = (const float*)d_in[5];
    const float* g1w  = (const float*)d_in[6];
    const float* g1as = (const float*)d_in[7];
    const float* g1ad = (const float*)d_in[8];
    const float* g1b  = (const float*)d_in[9];
    const float* g2w  = (const float*)d_in[10];
    const float* g2as = (const float*)d_in[11];
    const float* g2ad = (const float*)d_in[12];
    const float* g2b  = (const float*)d_in[13];
    const float* g3w  = (const float*)d_in[14];
    const float* g3as = (const float*)d_in[15];
    const float* g3ad = (const float*)d_in[16];
    const float* g3b  = (const float*)d_in[17];
    float* out = (float*)d_out;

    float *bufA, *ssrc, *sdst;
    __half *h16a, *h16b, *h16c, *w1h, *w2h, *g1wh, *g2wh;
    int *deg, *offs, *cursor, *csr;
    cudaGetSymbolAddress((void**)&bufA, g_bufA);
    cudaGetSymbolAddress((void**)&h16a, g_h16a);
    cudaGetSymbolAddress((void**)&h16b, g_h16b);
    cudaGetSymbolAddress((void**)&h16c, g_h16c);
    cudaGetSymbolAddress((void**)&ssrc, g_ssrc);
    cudaGetSymbolAddress((void**)&sdst, g_sdst);
    cudaGetSymbolAddress((void**)&deg, g_deg);
    cudaGetSymbolAddress((void**)&offs, g_offs);
    cudaGetSymbolAddress((void**)&cursor, g_cursor);
    cudaGetSymbolAddress((void**)&csr, g_csr);
    cudaGetSymbolAddress((void**)&w1h, g_w1h);
    cudaGetSymbolAddress((void**)&w2h, g_w2h);
    cudaGetSymbolAddress((void**)&g1wh, g_g1wh);
    cudaGetSymbolAddress((void**)&g2wh, g_g2wh);

    const int M = NN;

    // ---------------- fp16 conversion (x + weights) -------------------------
    f32_to_f16_vec4<<<(NN * 256 / 4 + 255) / 256, 256>>>(x, h16a, NN * 256 / 4);
    f32_to_f16_vec4<<<(256 * 128 / 4 + 255) / 256, 256>>>(w1, w1h, 256 * 128 / 4);
    f32_to_f16_vec4<<<(128 * 128 / 4 + 255) / 256, 256>>>(w2, w2h, 128 * 128 / 4);
    f32_to_f16_vec4<<<(128 * 256 / 4 + 255) / 256, 256>>>(g1w, g1wh, 128 * 256 / 4);
    f32_to_f16_vec4<<<(256 * 128 / 4 + 255) / 256, 256>>>(g2w, g2wh, 256 * 128 / 4);

    // ---------------- CSR build (once, reused by all 3 GAT layers) ----------
    cudaMemsetAsync(deg, 0, NN * sizeof(int));
    deg_count_kernel<<<(NT + 255) / 256, 256>>>(ei, deg);
    scan_kernel<<<1, 1024>>>(deg, offs, cursor);
    csr_fill_kernel<<<(NT + 255) / 256, 256>>>(ei, cursor, csr);

    // ---------------- MLP ----------------
    run_hgemm(h16a, w1h, b1, h16b, M, 256, 128, 1);   // h0 -> b
    run_hgemm(h16b, w2h, b2, h16c, M, 128, 128, 1);   // h1 -> c

    // ---------------- GAT1: H=4, D=64, concat (scores fused in GEMM) --------
    run_hgemm(h16c, g1wh, nullptr, h16a, M, 128, 256, 0,
              g1as, g1ad, ssrc, sdst, 4);                       // xh1 -> a
    gat_aggregate<4, 0><<<(NN + 7) / 8, 256>>>(offs, csr, h16a, ssrc, sdst, g1b, h16b);

    // ---------------- GAT2: H=2, D=64, mean --------------------------------
    run_hgemm(h16b, g2wh, nullptr, h16c, M, 256, 128, 0,
              g2as, g2ad, ssrc, sdst, 2);                       // xh2 -> c
    gat_aggregate<2, 1><<<(NN + 15) / 16, 256>>>(offs, csr, h16c, ssrc, sdst, g2b, bufA);

    // ---------------- GAT3: H=1, D=64 --------------------------------------
    {
        dim3 grid(1, (M + 63) / 64);
        sgemm_kernel<<<grid, 256>>>(bufA, g3w, h16a, M, 64, 64,
                                    g3as, g3ad, ssrc, sdst);    // xh3 -> a
    }
    gat_aggregate<1, 2><<<(NN + 31) / 32, 256>>>(offs, csr, h16a, ssrc, sdst, g3b, out);
}